// round 1
// baseline (speedup 1.0000x reference)
#include <cuda_runtime.h>
#include <math.h>

// Problem constants
#define BB 4
#define TT 2048
#define BT (BB*TT)     // 8192
#define FF 512
#define HS 4
#define CS0 31
#define CS1 61
#define HALF0 15
#define HALF1 30

// Scratch (device globals: alloc-free rule)
__device__ float g_rq0[BT*FF];
__device__ float g_rq1[BT*FF];
__device__ float g_v0 [BT*FF];
__device__ float g_v1 [BT*FF];
__device__ float g_mix[BT*FF];
__device__ float g_attn0[BT*HS*CS0];
__device__ float g_attn1[BT*HS*CS1];

// ---------------------------------------------------------------------------
// C[M,N] = act( A[M,K] @ Bt[N,K]^T ),  A,Bt,C row-major.
// Tile 64x64x16, 256 threads, 4x4 microtile per thread.
// M % 64 == 0, K % 16 == 0 assumed. N guarded.
// ---------------------------------------------------------------------------
__global__ __launch_bounds__(256)
void gemm_tn(const float* __restrict__ A, const float* __restrict__ Bt,
             float* __restrict__ C, int M, int N, int K, int do_relu)
{
    const int BM = 64, BN = 64, BK = 16;
    __shared__ float As[BK][BM];
    __shared__ float Bs[BK][BN];

    const int bm = blockIdx.y * BM;
    const int bn = blockIdx.x * BN;
    const int t  = threadIdx.x;
    const int tx = t & 15;      // 0..15 -> n
    const int ty = t >> 4;      // 0..15 -> m

    const int lrow = t >> 2;        // 0..63
    const int lcol = (t & 3) * 4;   // 0,4,8,12

    float acc[4][4];
#pragma unroll
    for (int i = 0; i < 4; i++)
#pragma unroll
        for (int j = 0; j < 4; j++) acc[i][j] = 0.f;

    for (int k0 = 0; k0 < K; k0 += BK) {
        // A tile -> As[k][m] (transposed store)
        float4 av = *(const float4*)&A[(size_t)(bm + lrow) * K + k0 + lcol];
        As[lcol + 0][lrow] = av.x;
        As[lcol + 1][lrow] = av.y;
        As[lcol + 2][lrow] = av.z;
        As[lcol + 3][lrow] = av.w;

        // B tile -> Bs[k][n]
        int nrow = bn + lrow;
        float4 bv = make_float4(0.f, 0.f, 0.f, 0.f);
        if (nrow < N)
            bv = *(const float4*)&Bt[(size_t)nrow * K + k0 + lcol];
        Bs[lcol + 0][lrow] = bv.x;
        Bs[lcol + 1][lrow] = bv.y;
        Bs[lcol + 2][lrow] = bv.z;
        Bs[lcol + 3][lrow] = bv.w;

        __syncthreads();

#pragma unroll
        for (int k = 0; k < BK; k++) {
            float4 a4 = *(const float4*)&As[k][ty * 4];
            float4 b4 = *(const float4*)&Bs[k][tx * 4];
            float a[4] = {a4.x, a4.y, a4.z, a4.w};
            float b[4] = {b4.x, b4.y, b4.z, b4.w};
#pragma unroll
            for (int i = 0; i < 4; i++)
#pragma unroll
                for (int j = 0; j < 4; j++)
                    acc[i][j] = fmaf(a[i], b[j], acc[i][j]);
        }
        __syncthreads();
    }

#pragma unroll
    for (int i = 0; i < 4; i++) {
        int m = bm + ty * 4 + i;
#pragma unroll
        for (int j = 0; j < 4; j++) {
            int n = bn + tx * 4 + j;
            if (n < N) {
                float v = acc[i][j];
                if (do_relu) v = fmaxf(v, 0.f);
                C[(size_t)m * N + n] = v;
            }
        }
    }
}

// ---------------------------------------------------------------------------
// Softmax over last dim (cs <= 61). One warp per (bt, head) row.
// attn layout: contiguous rows of length cs (rows = BT*HS).
// ---------------------------------------------------------------------------
__global__ void softmax_k(float* __restrict__ attn, int rows, int cs)
{
    int warp = (blockIdx.x * blockDim.x + threadIdx.x) >> 5;
    int lane = threadIdx.x & 31;
    if (warp >= rows) return;
    float* p = attn + (size_t)warp * cs;

    float v0 = (lane      < cs) ? p[lane]      : -INFINITY;
    float v1 = (lane + 32 < cs) ? p[lane + 32] : -INFINITY;
    float m = fmaxf(v0, v1);
#pragma unroll
    for (int o = 16; o > 0; o >>= 1)
        m = fmaxf(m, __shfl_xor_sync(0xFFFFFFFFu, m, o));

    float e0 = (lane      < cs) ? __expf(v0 - m) : 0.f;
    float e1 = (lane + 32 < cs) ? __expf(v1 - m) : 0.f;
    float s = e0 + e1;
#pragma unroll
    for (int o = 16; o > 0; o >>= 1)
        s += __shfl_xor_sync(0xFFFFFFFFu, s, o);

    float inv = 1.f / s;
    if (lane      < cs) p[lane]      = e0 * inv;
    if (lane + 32 < cs) p[lane + 32] = e1 * inv;
}

// ---------------------------------------------------------------------------
// Windowed attention apply + scale mix.
// Block = one (b,t); 512 threads = feature f. h = f >> 7.
// g_mix[bt,f] = sw0 * sum_c a0[h,c]*v0[b, t+c-15, f]
//             + sw1 * sum_c a1[h,c]*v1[b, t+c-30, f]
// ---------------------------------------------------------------------------
__global__ __launch_bounds__(512)
void window_k(const float* __restrict__ sw_in)
{
    __shared__ float sa0[HS * CS0];
    __shared__ float sa1[HS * CS1];
    __shared__ float ssw[2];

    int bt = blockIdx.x;
    int b  = bt / TT;
    int tt = bt - b * TT;
    int f  = threadIdx.x;

    if (f < HS * CS0) sa0[f] = g_attn0[(size_t)bt * (HS * CS0) + f];
    if (f < HS * CS1) sa1[f] = g_attn1[(size_t)bt * (HS * CS1) + f];
    if (f == 0) {
        float a = sw_in[0], c = sw_in[1];
        float mx = fmaxf(a, c);
        float ea = __expf(a - mx), ec = __expf(c - mx);
        float inv = 1.f / (ea + ec);
        ssw[0] = ea * inv;
        ssw[1] = ec * inv;
    }
    __syncthreads();

    int h = f >> 7;
    const float* a0 = sa0 + h * CS0;
    const float* a1 = sa1 + h * CS1;
    const float* v0b = g_v0 + ((size_t)b * TT) * FF + f;
    const float* v1b = g_v1 + ((size_t)b * TT) * FF + f;

    float acc0 = 0.f;
#pragma unroll
    for (int c = 0; c < CS0; c++) {
        int tp = tt + c - HALF0;
        if ((unsigned)tp < (unsigned)TT)
            acc0 = fmaf(a0[c], v0b[(size_t)tp * FF], acc0);
    }
    float acc1 = 0.f;
#pragma unroll
    for (int c = 0; c < CS1; c++) {
        int tp = tt + c - HALF1;
        if ((unsigned)tp < (unsigned)TT)
            acc1 = fmaf(a1[c], v1b[(size_t)tp * FF], acc1);
    }

    g_mix[(size_t)bt * FF + f] = ssw[0] * acc0 + ssw[1] * acc1;
}

// ---------------------------------------------------------------------------
extern "C" void kernel_launch(void* const* d_in, const int* in_sizes, int n_in,
                              void* d_out, int out_size)
{
    const float* query = (const float*)d_in[0];
    // d_in[1] = key (unused by reference)
    const float* value = (const float*)d_in[2];
    const float* w1_0  = (const float*)d_in[3];
    const float* w1_1  = (const float*)d_in[4];
    const float* w2_0  = (const float*)d_in[5];
    const float* w2_1  = (const float*)d_in[6];
    const float* w3_0  = (const float*)d_in[7];
    const float* w3_1  = (const float*)d_in[8];
    const float* sw    = (const float*)d_in[9];
    const float* w_out = (const float*)d_in[10];
    float* out = (float*)d_out;

    float *rq0, *rq1, *v0, *v1, *mix, *a0, *a1;
    cudaGetSymbolAddress((void**)&rq0, g_rq0);
    cudaGetSymbolAddress((void**)&rq1, g_rq1);
    cudaGetSymbolAddress((void**)&v0,  g_v0);
    cudaGetSymbolAddress((void**)&v1,  g_v1);
    cudaGetSymbolAddress((void**)&mix, g_mix);
    cudaGetSymbolAddress((void**)&a0,  g_attn0);
    cudaGetSymbolAddress((void**)&a1,  g_attn1);

    dim3 gFull(FF / 64, BT / 64);      // 8 x 128
    dim3 gL0((HS * CS0 + 63) / 64, BT / 64);   // 2 x 128
    dim3 gL1((HS * CS1 + 63) / 64, BT / 64);   // 4 x 128

    // q = relu(query @ w1^T), v = value @ w3^T
    gemm_tn<<<gFull, 256>>>(query, w1_0, rq0, BT, FF, FF, 1);
    gemm_tn<<<gFull, 256>>>(query, w1_1, rq1, BT, FF, FF, 1);
    gemm_tn<<<gFull, 256>>>(value, w3_0, v0,  BT, FF, FF, 0);
    gemm_tn<<<gFull, 256>>>(value, w3_1, v1,  BT, FF, FF, 0);

    // logits = relu(q) @ w2^T
    gemm_tn<<<gL0, 256>>>(rq0, w2_0, a0, BT, HS * CS0, FF, 0);
    gemm_tn<<<gL1, 256>>>(rq1, w2_1, a1, BT, HS * CS1, FF, 0);

    // softmax over cs per (bt, head): rows = BT*HS, 8 warps per block
    int rows = BT * HS;
    softmax_k<<<(rows * 32 + 255) / 256, 256>>>(a0, rows, CS0);
    softmax_k<<<(rows * 32 + 255) / 256, 256>>>(a1, rows, CS1);

    // window apply + scale mixing
    window_k<<<BT, 512>>>(sw);

    // final projection
    gemm_tn<<<gFull, 256>>>(mix, w_out, out, BT, FF, FF, 0);
}

// round 2
// speedup vs baseline: 2.0418x; 2.0418x over previous
#include <cuda_runtime.h>
#include <math.h>
#include <stdint.h>

// Problem constants
#define BB 4
#define TT 2048
#define BT (BB*TT)     // 8192
#define FF 512
#define HS 4
#define CS0 31
#define CS1 61
#define HALF0 15
#define HALF1 30
#define TCH 8          // tokens per window block

// Scratch (device globals: alloc-free rule)
__device__ float g_rq0[BT*FF];
__device__ float g_rq1[BT*FF];
__device__ float g_v0 [BT*FF];
__device__ float g_v1 [BT*FF];
__device__ float g_mix[BT*FF];
__device__ float g_attn0[BT*HS*CS0];
__device__ float g_attn1[BT*HS*CS1];

__device__ __forceinline__ unsigned f2tf(float x) {
    unsigned r;
    asm("cvt.rna.tf32.f32 %0, %1;" : "=r"(r) : "f"(x));
    return r;
}

__device__ __forceinline__ void mma_tf32(float c[4], unsigned a0, unsigned a1,
                                         unsigned a2, unsigned a3,
                                         unsigned b0, unsigned b1) {
    asm volatile(
        "mma.sync.aligned.m16n8k8.row.col.f32.tf32.tf32.f32 "
        "{%0,%1,%2,%3}, {%4,%5,%6,%7}, {%8,%9}, {%0,%1,%2,%3};"
        : "+f"(c[0]), "+f"(c[1]), "+f"(c[2]), "+f"(c[3])
        : "r"(a0), "r"(a1), "r"(a2), "r"(a3), "r"(b0), "r"(b1));
}

// ---------------------------------------------------------------------------
// C[M,N] = act( A[M,K] @ Bt[N,K]^T ) via tf32 mma.sync.
// Block tile 128x64x32, 8 warps, warp tile 32x32 (2x4 of m16n8k8).
// M % 128 == 0, K % 32 == 0 assumed. N guarded (zero-padded in smem).
// ---------------------------------------------------------------------------
__global__ __launch_bounds__(256)
void gemm_mma(const float* __restrict__ A, const float* __restrict__ Bt,
              float* __restrict__ C, int M, int N, int K, int do_relu)
{
    // stride 36: 36 mod 32 = 4 -> fragment LDS bank = 4*row + col, conflict-free
    __shared__ unsigned As[128][36];
    __shared__ unsigned Bs[64][36];

    const int tid  = threadIdx.x;
    const int lane = tid & 31;
    const int warp = tid >> 5;
    const int wm   = warp >> 1;   // 0..3
    const int wn   = warp & 1;    // 0..1
    const int bm   = blockIdx.y * 128;
    const int bn   = blockIdx.x * 64;

    const int gid  = lane >> 2;   // 0..7
    const int quad = lane & 3;    // 0..3

    float acc[2][4][4];
#pragma unroll
    for (int mt = 0; mt < 2; mt++)
#pragma unroll
        for (int nt = 0; nt < 4; nt++)
#pragma unroll
            for (int i = 0; i < 4; i++) acc[mt][nt][i] = 0.f;

    for (int k0 = 0; k0 < K; k0 += 32) {
        // A tile: 128 rows x 8 float4 = 1024 f4, 4 per thread
#pragma unroll
        for (int i = 0; i < 4; i++) {
            int id = tid + i * 256;
            int r  = id >> 3;
            int c  = (id & 7) * 4;
            float4 v = *(const float4*)&A[(size_t)(bm + r) * K + k0 + c];
            *(uint4*)&As[r][c] = make_uint4(f2tf(v.x), f2tf(v.y), f2tf(v.z), f2tf(v.w));
        }
        // B tile: 64 rows x 8 float4 = 512 f4, 2 per thread
#pragma unroll
        for (int i = 0; i < 2; i++) {
            int id = tid + i * 256;
            int r  = id >> 3;
            int c  = (id & 7) * 4;
            float4 v = make_float4(0.f, 0.f, 0.f, 0.f);
            if (bn + r < N)
                v = *(const float4*)&Bt[(size_t)(bn + r) * K + k0 + c];
            *(uint4*)&Bs[r][c] = make_uint4(f2tf(v.x), f2tf(v.y), f2tf(v.z), f2tf(v.w));
        }
        __syncthreads();

#pragma unroll
        for (int kk = 0; kk < 32; kk += 8) {
            unsigned a[2][4], b[4][2];
#pragma unroll
            for (int mt = 0; mt < 2; mt++) {
                int r = wm * 32 + mt * 16 + gid;
                int c = kk + quad;
                a[mt][0] = As[r][c];
                a[mt][1] = As[r + 8][c];
                a[mt][2] = As[r][c + 4];
                a[mt][3] = As[r + 8][c + 4];
            }
#pragma unroll
            for (int nt = 0; nt < 4; nt++) {
                int n = wn * 32 + nt * 8 + gid;
                int c = kk + quad;
                b[nt][0] = Bs[n][c];
                b[nt][1] = Bs[n][c + 4];
            }
#pragma unroll
            for (int mt = 0; mt < 2; mt++)
#pragma unroll
                for (int nt = 0; nt < 4; nt++)
                    mma_tf32(acc[mt][nt], a[mt][0], a[mt][1], a[mt][2], a[mt][3],
                             b[nt][0], b[nt][1]);
        }
        __syncthreads();
    }

    // Epilogue
#pragma unroll
    for (int mt = 0; mt < 2; mt++) {
        int r0 = bm + wm * 32 + mt * 16 + gid;
#pragma unroll
        for (int nt = 0; nt < 4; nt++) {
            int c0 = bn + wn * 32 + nt * 8 + quad * 2;
            float v0 = acc[mt][nt][0], v1 = acc[mt][nt][1];
            float v2 = acc[mt][nt][2], v3 = acc[mt][nt][3];
            if (do_relu) {
                v0 = fmaxf(v0, 0.f); v1 = fmaxf(v1, 0.f);
                v2 = fmaxf(v2, 0.f); v3 = fmaxf(v3, 0.f);
            }
            if (c0 < N) {
                C[(size_t)r0 * N + c0]       = v0;
                C[(size_t)(r0 + 8) * N + c0] = v2;
            }
            if (c0 + 1 < N) {
                C[(size_t)r0 * N + c0 + 1]       = v1;
                C[(size_t)(r0 + 8) * N + c0 + 1] = v3;
            }
        }
    }
}

// ---------------------------------------------------------------------------
// Softmax over last dim (cs <= 61). One warp per (bt, head) row.
// ---------------------------------------------------------------------------
__global__ void softmax_k(float* __restrict__ attn, int rows, int cs)
{
    int warp = (blockIdx.x * blockDim.x + threadIdx.x) >> 5;
    int lane = threadIdx.x & 31;
    if (warp >= rows) return;
    float* p = attn + (size_t)warp * cs;

    float v0 = (lane      < cs) ? p[lane]      : -INFINITY;
    float v1 = (lane + 32 < cs) ? p[lane + 32] : -INFINITY;
    float m = fmaxf(v0, v1);
#pragma unroll
    for (int o = 16; o > 0; o >>= 1)
        m = fmaxf(m, __shfl_xor_sync(0xFFFFFFFFu, m, o));

    float e0 = (lane      < cs) ? __expf(v0 - m) : 0.f;
    float e1 = (lane + 32 < cs) ? __expf(v1 - m) : 0.f;
    float s = e0 + e1;
#pragma unroll
    for (int o = 16; o > 0; o >>= 1)
        s += __shfl_xor_sync(0xFFFFFFFFu, s, o);

    float inv = 1.f / s;
    if (lane      < cs) p[lane]      = e0 * inv;
    if (lane + 32 < cs) p[lane + 32] = e1 * inv;
}

// ---------------------------------------------------------------------------
// Windowed attention apply + scale mix, TCH=8 tokens per block.
// 512 threads = feature f; each v-row load feeds 8 outputs.
// ---------------------------------------------------------------------------
__global__ __launch_bounds__(512)
void window_k(const float* __restrict__ sw_in)
{
    __shared__ float sa0[TCH][HS * CS0];
    __shared__ float sa1[TCH][HS * CS1];
    __shared__ float ssw[2];

    int t0g = blockIdx.x * TCH;      // global bt start (TCH divides TT)
    int b   = t0g / TT;
    int t0  = t0g - b * TT;
    int f   = threadIdx.x;

    for (int i = f; i < TCH * HS * CS0; i += 512)
        ((float*)sa0)[i] = g_attn0[(size_t)t0g * (HS * CS0) + i];
    for (int i = f; i < TCH * HS * CS1; i += 512)
        ((float*)sa1)[i] = g_attn1[(size_t)t0g * (HS * CS1) + i];
    if (f == 0) {
        float a = sw_in[0], c = sw_in[1];
        float mx = fmaxf(a, c);
        float ea = __expf(a - mx), ec = __expf(c - mx);
        float inv = 1.f / (ea + ec);
        ssw[0] = ea * inv;
        ssw[1] = ec * inv;
    }
    __syncthreads();

    int h = f >> 7;
    const float* v0b = g_v0 + ((size_t)b * TT) * FF + f;
    const float* v1b = g_v1 + ((size_t)b * TT) * FF + f;

    float acc0[TCH], acc1[TCH];
#pragma unroll
    for (int j = 0; j < TCH; j++) { acc0[j] = 0.f; acc1[j] = 0.f; }

    for (int r = 0; r < TCH - 1 + CS0; r++) {
        int tp = t0 + r - HALF0;
        float v = ((unsigned)tp < (unsigned)TT) ? v0b[(size_t)tp * FF] : 0.f;
#pragma unroll
        for (int j = 0; j < TCH; j++) {
            int c = r - j;
            if ((unsigned)c < (unsigned)CS0)
                acc0[j] = fmaf(sa0[j][h * CS0 + c], v, acc0[j]);
        }
    }
    for (int r = 0; r < TCH - 1 + CS1; r++) {
        int tp = t0 + r - HALF1;
        float v = ((unsigned)tp < (unsigned)TT) ? v1b[(size_t)tp * FF] : 0.f;
#pragma unroll
        for (int j = 0; j < TCH; j++) {
            int c = r - j;
            if ((unsigned)c < (unsigned)CS1)
                acc1[j] = fmaf(sa1[j][h * CS1 + c], v, acc1[j]);
        }
    }

    float s0 = ssw[0], s1 = ssw[1];
#pragma unroll
    for (int j = 0; j < TCH; j++)
        g_mix[(size_t)(t0g + j) * FF + f] = s0 * acc0[j] + s1 * acc1[j];
}

// ---------------------------------------------------------------------------
extern "C" void kernel_launch(void* const* d_in, const int* in_sizes, int n_in,
                              void* d_out, int out_size)
{
    const float* query = (const float*)d_in[0];
    // d_in[1] = key (unused by reference)
    const float* value = (const float*)d_in[2];
    const float* w1_0  = (const float*)d_in[3];
    const float* w1_1  = (const float*)d_in[4];
    const float* w2_0  = (const float*)d_in[5];
    const float* w2_1  = (const float*)d_in[6];
    const float* w3_0  = (const float*)d_in[7];
    const float* w3_1  = (const float*)d_in[8];
    const float* sw    = (const float*)d_in[9];
    const float* w_out = (const float*)d_in[10];
    float* out = (float*)d_out;

    float *rq0, *rq1, *v0, *v1, *mix, *a0, *a1;
    cudaGetSymbolAddress((void**)&rq0, g_rq0);
    cudaGetSymbolAddress((void**)&rq1, g_rq1);
    cudaGetSymbolAddress((void**)&v0,  g_v0);
    cudaGetSymbolAddress((void**)&v1,  g_v1);
    cudaGetSymbolAddress((void**)&mix, g_mix);
    cudaGetSymbolAddress((void**)&a0,  g_attn0);
    cudaGetSymbolAddress((void**)&a1,  g_attn1);

    dim3 gFull(FF / 64, BT / 128);                   // 8 x 64
    dim3 gL0((HS * CS0 + 63) / 64, BT / 128);        // 2 x 64
    dim3 gL1((HS * CS1 + 63) / 64, BT / 128);        // 4 x 64

    // q = relu(query @ w1^T), v = value @ w3^T
    gemm_mma<<<gFull, 256>>>(query, w1_0, rq0, BT, FF, FF, 1);
    gemm_mma<<<gFull, 256>>>(query, w1_1, rq1, BT, FF, FF, 1);
    gemm_mma<<<gFull, 256>>>(value, w3_0, v0,  BT, FF, FF, 0);
    gemm_mma<<<gFull, 256>>>(value, w3_1, v1,  BT, FF, FF, 0);

    // logits = relu(q) @ w2^T
    gemm_mma<<<gL0, 256>>>(rq0, w2_0, a0, BT, HS * CS0, FF, 0);
    gemm_mma<<<gL1, 256>>>(rq1, w2_1, a1, BT, HS * CS1, FF, 0);

    // softmax per (bt, head)
    int rows = BT * HS;
    softmax_k<<<(rows * 32 + 255) / 256, 256>>>(a0, rows, CS0);
    softmax_k<<<(rows * 32 + 255) / 256, 256>>>(a1, rows, CS1);

    // window apply + scale mixing (8 tokens per block)
    window_k<<<BT / TCH, 512>>>(sw);

    // final projection
    gemm_mma<<<gFull, 256>>>(mix, w_out, out, BT, FF, FF, 0);
}

// round 3
// speedup vs baseline: 2.5509x; 1.2493x over previous
#include <cuda_runtime.h>
#include <math.h>
#include <stdint.h>

// Problem constants
#define BB 4
#define TT 2048
#define BT (BB*TT)     // 8192
#define FF 512
#define HS 4
#define CS0 31
#define CS1 61
#define HALF0 15
#define HALF1 30
#define TCH 16         // tokens per window block

#define W_SZ (FF*FF)
#define W2_0_SZ (HS*CS0*FF)   // 63488
#define W2_1_SZ (HS*CS1*FF)   // 124928
// g_wtf layout offsets
#define OFF_W1_0 0
#define OFF_W1_1 (W_SZ)
#define OFF_W3_0 (2*W_SZ)
#define OFF_W3_1 (3*W_SZ)
#define OFF_WOUT (4*W_SZ)
#define OFF_W2_0 (5*W_SZ)
#define OFF_W2_1 (5*W_SZ + W2_0_SZ)
#define WTF_TOTAL (5*W_SZ + W2_0_SZ + W2_1_SZ)

// Scratch (device globals: alloc-free rule)
__device__ float g_qtf[BT*FF];
__device__ float g_vtf[BT*FF];
__device__ float g_wtf[WTF_TOTAL];
__device__ float g_rq0[BT*FF];
__device__ float g_rq1[BT*FF];
__device__ float g_v0 [BT*FF];
__device__ float g_v1 [BT*FF];
__device__ float g_mix[BT*FF];
__device__ float g_attn0[BT*HS*CS0];
__device__ float g_attn1[BT*HS*CS1];

__device__ __forceinline__ unsigned f2tf(float x) {
    unsigned r;
    asm("cvt.rna.tf32.f32 %0, %1;" : "=r"(r) : "f"(x));
    return r;
}
__device__ __forceinline__ float f2tf_f(float x) {
    unsigned r = f2tf(x);
    return __uint_as_float(r);
}

__device__ __forceinline__ void mma_tf32(float c[4], unsigned a0, unsigned a1,
                                         unsigned a2, unsigned a3,
                                         unsigned b0, unsigned b1) {
    asm volatile(
        "mma.sync.aligned.m16n8k8.row.col.f32.tf32.tf32.f32 "
        "{%0,%1,%2,%3}, {%4,%5,%6,%7}, {%8,%9}, {%0,%1,%2,%3};"
        : "+f"(c[0]), "+f"(c[1]), "+f"(c[2]), "+f"(c[3])
        : "r"(a0), "r"(a1), "r"(a2), "r"(a3), "r"(b0), "r"(b1));
}

__device__ __forceinline__ void cp16(float* dst_smem, const float* src, bool pred) {
    unsigned d = (unsigned)__cvta_generic_to_shared(dst_smem);
    int sz = pred ? 16 : 0;
    asm volatile("cp.async.cg.shared.global [%0], [%1], 16, %2;"
                 :: "r"(d), "l"(src), "r"(sz));
}
__device__ __forceinline__ void cp_commit() {
    asm volatile("cp.async.commit_group;");
}

// ---------------------------------------------------------------------------
// tf32 prepass rounding: dst[i] = round_rna_tf32(src[i]) as fp32 bits
// ---------------------------------------------------------------------------
struct RDesc { const float* s; float* d; int n4; };
struct RArgs { RDesc r[9]; };

__global__ void round_k(RArgs a)
{
    RDesc t = a.r[blockIdx.z];
    int stride = gridDim.x * blockDim.x;
    for (int i = blockIdx.x * blockDim.x + threadIdx.x; i < t.n4; i += stride) {
        float4 v = ((const float4*)t.s)[i];
        uint4 u = make_uint4(f2tf(v.x), f2tf(v.y), f2tf(v.z), f2tf(v.w));
        ((uint4*)t.d)[i] = u;
    }
}

// ---------------------------------------------------------------------------
// Batched tf32 GEMM: C[M,N] = act( A[M,K] @ B[N,K]^T ), cp.async 3-stage.
// Block tile 128x64x32, 8 warps, warp tile 32x32 (2x4 m16n8k8 frags).
// blockIdx.z selects descriptor. M=8192, K=512. N guarded.
// flags: bit0 = relu, bit1 = round output to tf32
// ---------------------------------------------------------------------------
struct GemmDesc { const float* A; const float* B; float* C; int N; int flags; };
struct GemmArgs { GemmDesc d[4]; };

#define BM 128
#define BN 64
#define BK 32
#define STR 36
#define A_STG (BM*STR)   // 4608 floats per stage
#define B_STG (BN*STR)   // 2304 floats per stage
#define GEMM_SMEM (3*(A_STG + B_STG)*4)   // 82944 bytes

__global__ __launch_bounds__(256)
void gemm_mma(GemmArgs args, int K)
{
    GemmDesc g = args.d[blockIdx.z];
    const int bn = blockIdx.x * BN;
    if (bn >= g.N) return;
    const int bm = blockIdx.y * BM;

    extern __shared__ float sm[];
    float* As = sm;                // 3 stages
    float* Bs = sm + 3 * A_STG;    // 3 stages

    const int tid  = threadIdx.x;
    const int lane = tid & 31;
    const int warp = tid >> 5;
    const int wm   = warp >> 1;   // 0..3
    const int wn   = warp & 1;    // 0..1
    const int gid  = lane >> 2;   // 0..7
    const int quad = lane & 3;    // 0..3

    const int NT = K / BK;        // 16

    // stage loader
    auto load_stage = [&](int s, int k0) {
        float* a = As + s * A_STG;
#pragma unroll
        for (int i = 0; i < 4; i++) {
            int id = tid + i * 256;
            int r  = id >> 3;
            int c  = (id & 7) * 4;
            cp16(a + r * STR + c, g.A + (size_t)(bm + r) * K + k0 + c, true);
        }
        float* b = Bs + s * B_STG;
#pragma unroll
        for (int i = 0; i < 2; i++) {
            int id = tid + i * 256;
            int r  = id >> 3;
            int c  = (id & 7) * 4;
            bool ok = (bn + r) < g.N;
            const float* src = ok ? (g.B + (size_t)(bn + r) * K + k0 + c) : g.B;
            cp16(b + r * STR + c, src, ok);
        }
        cp_commit();
    };

    float acc[2][4][4];
#pragma unroll
    for (int mt = 0; mt < 2; mt++)
#pragma unroll
        for (int nt = 0; nt < 4; nt++)
#pragma unroll
            for (int i = 0; i < 4; i++) acc[mt][nt][i] = 0.f;

    // prologue: stages 0,1
    load_stage(0, 0);
    load_stage(1, BK);

    for (int kt = 0; kt < NT; kt++) {
        if (kt == NT - 1)
            asm volatile("cp.async.wait_group 0;");
        else
            asm volatile("cp.async.wait_group 1;");
        __syncthreads();

        if (kt + 2 < NT)
            load_stage((kt + 2) % 3, (kt + 2) * BK);

        const unsigned* Au = (const unsigned*)(As + (kt % 3) * A_STG);
        const unsigned* Bu = (const unsigned*)(Bs + (kt % 3) * B_STG);

#pragma unroll
        for (int kk = 0; kk < BK; kk += 8) {
            unsigned a[2][4], b[4][2];
#pragma unroll
            for (int mt = 0; mt < 2; mt++) {
                int r = wm * 32 + mt * 16 + gid;
                int c = kk + quad;
                a[mt][0] = Au[r * STR + c];
                a[mt][1] = Au[(r + 8) * STR + c];
                a[mt][2] = Au[r * STR + c + 4];
                a[mt][3] = Au[(r + 8) * STR + c + 4];
            }
#pragma unroll
            for (int nt = 0; nt < 4; nt++) {
                int n = wn * 32 + nt * 8 + gid;
                int c = kk + quad;
                b[nt][0] = Bu[n * STR + c];
                b[nt][1] = Bu[n * STR + c + 4];
            }
#pragma unroll
            for (int mt = 0; mt < 2; mt++)
#pragma unroll
                for (int nt = 0; nt < 4; nt++)
                    mma_tf32(acc[mt][nt], a[mt][0], a[mt][1], a[mt][2], a[mt][3],
                             b[nt][0], b[nt][1]);
        }
        __syncthreads();
    }

    const int relu = g.flags & 1;
    const int rnd  = g.flags & 2;
#pragma unroll
    for (int mt = 0; mt < 2; mt++) {
        int r0 = bm + wm * 32 + mt * 16 + gid;
#pragma unroll
        for (int nt = 0; nt < 4; nt++) {
            int c0 = bn + wn * 32 + nt * 8 + quad * 2;
            float v0 = acc[mt][nt][0], v1 = acc[mt][nt][1];
            float v2 = acc[mt][nt][2], v3 = acc[mt][nt][3];
            if (relu) {
                v0 = fmaxf(v0, 0.f); v1 = fmaxf(v1, 0.f);
                v2 = fmaxf(v2, 0.f); v3 = fmaxf(v3, 0.f);
            }
            if (rnd) {
                v0 = f2tf_f(v0); v1 = f2tf_f(v1);
                v2 = f2tf_f(v2); v3 = f2tf_f(v3);
            }
            if (c0 < g.N) {
                g.C[(size_t)r0 * g.N + c0]       = v0;
                g.C[(size_t)(r0 + 8) * g.N + c0] = v2;
            }
            if (c0 + 1 < g.N) {
                g.C[(size_t)r0 * g.N + c0 + 1]       = v1;
                g.C[(size_t)(r0 + 8) * g.N + c0 + 1] = v3;
            }
        }
    }
}

// ---------------------------------------------------------------------------
// Softmax over last dim (cs <= 61). One warp per (bt, head) row.
// blockIdx.z: 0 -> attn0/cs0, 1 -> attn1/cs1
// ---------------------------------------------------------------------------
__global__ void softmax_k(float* __restrict__ a0p, float* __restrict__ a1p, int rows)
{
    int cs = blockIdx.z ? CS1 : CS0;
    float* attn = blockIdx.z ? a1p : a0p;
    int warp = (blockIdx.x * blockDim.x + threadIdx.x) >> 5;
    int lane = threadIdx.x & 31;
    if (warp >= rows) return;
    float* p = attn + (size_t)warp * cs;

    float v0 = (lane      < cs) ? p[lane]      : -INFINITY;
    float v1 = (lane + 32 < cs) ? p[lane + 32] : -INFINITY;
    float m = fmaxf(v0, v1);
#pragma unroll
    for (int o = 16; o > 0; o >>= 1)
        m = fmaxf(m, __shfl_xor_sync(0xFFFFFFFFu, m, o));

    float e0 = (lane      < cs) ? __expf(v0 - m) : 0.f;
    float e1 = (lane + 32 < cs) ? __expf(v1 - m) : 0.f;
    float s = e0 + e1;
#pragma unroll
    for (int o = 16; o > 0; o >>= 1)
        s += __shfl_xor_sync(0xFFFFFFFFu, s, o);

    float inv = 1.f / s;
    if (lane      < cs) p[lane]      = e0 * inv;
    if (lane + 32 < cs) p[lane + 32] = e1 * inv;
}

// ---------------------------------------------------------------------------
// Windowed attention apply + scale mix, TCH tokens per block.
// 512 threads = feature f; each v-row load feeds TCH outputs.
// Output mix is rounded to tf32 (it is the A of the final GEMM).
// ---------------------------------------------------------------------------
__global__ __launch_bounds__(512)
void window_k(const float* __restrict__ sw_in)
{
    __shared__ float sa0[TCH][HS * CS0];
    __shared__ float sa1[TCH][HS * CS1];
    __shared__ float ssw[2];

    int t0g = blockIdx.x * TCH;      // global bt start (TCH divides TT)
    int b   = t0g / TT;
    int t0  = t0g - b * TT;
    int f   = threadIdx.x;

    for (int i = f; i < TCH * HS * CS0; i += 512)
        ((float*)sa0)[i] = g_attn0[(size_t)t0g * (HS * CS0) + i];
    for (int i = f; i < TCH * HS * CS1; i += 512)
        ((float*)sa1)[i] = g_attn1[(size_t)t0g * (HS * CS1) + i];
    if (f == 0) {
        float a = sw_in[0], c = sw_in[1];
        float mx = fmaxf(a, c);
        float ea = __expf(a - mx), ec = __expf(c - mx);
        float inv = 1.f / (ea + ec);
        ssw[0] = ea * inv;
        ssw[1] = ec * inv;
    }
    __syncthreads();

    int h = f >> 7;
    const float* v0b = g_v0 + ((size_t)b * TT) * FF + f;
    const float* v1b = g_v1 + ((size_t)b * TT) * FF + f;

    float acc0[TCH], acc1[TCH];
#pragma unroll
    for (int j = 0; j < TCH; j++) { acc0[j] = 0.f; acc1[j] = 0.f; }

    for (int r = 0; r < TCH - 1 + CS0; r++) {
        int tp = t0 + r - HALF0;
        float v = ((unsigned)tp < (unsigned)TT) ? v0b[(size_t)tp * FF] : 0.f;
#pragma unroll
        for (int j = 0; j < TCH; j++) {
            int c = r - j;
            if ((unsigned)c < (unsigned)CS0)
                acc0[j] = fmaf(sa0[j][h * CS0 + c], v, acc0[j]);
        }
    }
    for (int r = 0; r < TCH - 1 + CS1; r++) {
        int tp = t0 + r - HALF1;
        float v = ((unsigned)tp < (unsigned)TT) ? v1b[(size_t)tp * FF] : 0.f;
#pragma unroll
        for (int j = 0; j < TCH; j++) {
            int c = r - j;
            if ((unsigned)c < (unsigned)CS1)
                acc1[j] = fmaf(sa1[j][h * CS1 + c], v, acc1[j]);
        }
    }

    float s0 = ssw[0], s1 = ssw[1];
#pragma unroll
    for (int j = 0; j < TCH; j++)
        g_mix[(size_t)(t0g + j) * FF + f] = f2tf_f(s0 * acc0[j] + s1 * acc1[j]);
}

// ---------------------------------------------------------------------------
extern "C" void kernel_launch(void* const* d_in, const int* in_sizes, int n_in,
                              void* d_out, int out_size)
{
    const float* query = (const float*)d_in[0];
    // d_in[1] = key (unused by reference)
    const float* value = (const float*)d_in[2];
    const float* w1_0  = (const float*)d_in[3];
    const float* w1_1  = (const float*)d_in[4];
    const float* w2_0  = (const float*)d_in[5];
    const float* w2_1  = (const float*)d_in[6];
    const float* w3_0  = (const float*)d_in[7];
    const float* w3_1  = (const float*)d_in[8];
    const float* sw    = (const float*)d_in[9];
    const float* w_out = (const float*)d_in[10];
    float* out = (float*)d_out;

    float *qtf, *vtf, *wtf, *rq0, *rq1, *v0, *v1, *mix, *a0, *a1;
    cudaGetSymbolAddress((void**)&qtf, g_qtf);
    cudaGetSymbolAddress((void**)&vtf, g_vtf);
    cudaGetSymbolAddress((void**)&wtf, g_wtf);
    cudaGetSymbolAddress((void**)&rq0, g_rq0);
    cudaGetSymbolAddress((void**)&rq1, g_rq1);
    cudaGetSymbolAddress((void**)&v0,  g_v0);
    cudaGetSymbolAddress((void**)&v1,  g_v1);
    cudaGetSymbolAddress((void**)&mix, g_mix);
    cudaGetSymbolAddress((void**)&a0,  g_attn0);
    cudaGetSymbolAddress((void**)&a1,  g_attn1);

    static bool attr_done = false;
    if (!attr_done) {
        cudaFuncSetAttribute(gemm_mma, cudaFuncAttributeMaxDynamicSharedMemorySize,
                             GEMM_SMEM);
        attr_done = true;
    }

    // 1) tf32 rounding prepass
    RArgs ra;
    ra.r[0] = {query, qtf, BT * FF / 4};
    ra.r[1] = {value, vtf, BT * FF / 4};
    ra.r[2] = {w1_0, wtf + OFF_W1_0, W_SZ / 4};
    ra.r[3] = {w1_1, wtf + OFF_W1_1, W_SZ / 4};
    ra.r[4] = {w3_0, wtf + OFF_W3_0, W_SZ / 4};
    ra.r[5] = {w3_1, wtf + OFF_W3_1, W_SZ / 4};
    ra.r[6] = {w_out, wtf + OFF_WOUT, W_SZ / 4};
    ra.r[7] = {w2_0, wtf + OFF_W2_0, W2_0_SZ / 4};
    ra.r[8] = {w2_1, wtf + OFF_W2_1, W2_1_SZ / 4};
    round_k<<<dim3(192, 1, 9), 256>>>(ra);

    // 2) 4 big GEMMs in one launch
    GemmArgs gb;
    gb.d[0] = {qtf, wtf + OFF_W1_0, rq0, FF, 1 | 2};  // relu + tf32-round
    gb.d[1] = {qtf, wtf + OFF_W1_1, rq1, FF, 1 | 2};
    gb.d[2] = {vtf, wtf + OFF_W3_0, v0,  FF, 0};
    gb.d[3] = {vtf, wtf + OFF_W3_1, v1,  FF, 0};
    gemm_mma<<<dim3(FF / BN, BT / BM, 4), 256, GEMM_SMEM>>>(gb, FF);

    // 3) logits GEMMs in one launch
    GemmArgs gl;
    gl.d[0] = {rq0, wtf + OFF_W2_0, a0, HS * CS0, 0};
    gl.d[1] = {rq1, wtf + OFF_W2_1, a1, HS * CS1, 0};
    gl.d[2] = gl.d[0]; gl.d[3] = gl.d[0];
    gemm_mma<<<dim3((HS * CS1 + BN - 1) / BN, BT / BM, 2), 256, GEMM_SMEM>>>(gl, FF);

    // 4) softmax per (bt, head), both scales in one launch
    int rows = BT * HS;
    softmax_k<<<dim3((rows * 32 + 255) / 256, 1, 2), 256>>>(a0, a1, rows);

    // 5) window apply + scale mixing
    window_k<<<BT / TCH, 512>>>(sw);

    // 6) final projection
    GemmArgs gf;
    gf.d[0] = {mix, wtf + OFF_WOUT, out, FF, 0};
    gf.d[1] = gf.d[0]; gf.d[2] = gf.d[0]; gf.d[3] = gf.d[0];
    gemm_mma<<<dim3(FF / BN, BT / BM, 1), 256, GEMM_SMEM>>>(gf, FF);
}

// round 4
// speedup vs baseline: 2.7351x; 1.0722x over previous
#include <cuda_runtime.h>
#include <math.h>
#include <stdint.h>

// Problem constants
#define BB 4
#define TT 2048
#define BT (BB*TT)     // 8192
#define FF 512
#define HS 4
#define CS0 31
#define CS1 61
#define HALF0 15
#define HALF1 30
#define TCH 16         // tokens per window block

// Scratch (device globals: alloc-free rule)
__device__ float g_rq0[BT*FF];
__device__ float g_rq1[BT*FF];
__device__ float g_v0 [BT*FF];
__device__ float g_v1 [BT*FF];
__device__ float g_mix[BT*FF];
__device__ float g_attn0[BT*HS*CS0];   // raw logits, softmaxed in window_k
__device__ float g_attn1[BT*HS*CS1];

__device__ __forceinline__ unsigned f2tf(float x) {
    unsigned r;
    asm("cvt.rna.tf32.f32 %0, %1;" : "=r"(r) : "f"(x));
    return r;
}

__device__ __forceinline__ void mma_tf32(float c[4], unsigned a0, unsigned a1,
                                         unsigned a2, unsigned a3,
                                         unsigned b0, unsigned b1) {
    asm volatile(
        "mma.sync.aligned.m16n8k8.row.col.f32.tf32.tf32.f32 "
        "{%0,%1,%2,%3}, {%4,%5,%6,%7}, {%8,%9}, {%0,%1,%2,%3};"
        : "+f"(c[0]), "+f"(c[1]), "+f"(c[2]), "+f"(c[3])
        : "r"(a0), "r"(a1), "r"(a2), "r"(a3), "r"(b0), "r"(b1));
}

__device__ __forceinline__ void cp16(float* dst_smem, const float* src, bool pred) {
    unsigned d = (unsigned)__cvta_generic_to_shared(dst_smem);
    int sz = pred ? 16 : 0;
    asm volatile("cp.async.cg.shared.global [%0], [%1], 16, %2;"
                 :: "r"(d), "l"(src), "r"(sz));
}
__device__ __forceinline__ void cp_commit() {
    asm volatile("cp.async.commit_group;");
}

// ---------------------------------------------------------------------------
// Batched tf32 GEMM: C[M,N] = act( A[M,K] @ B[N,K]^T ), raw fp32 inputs,
// cvt.rna.tf32 applied on fragment registers. cp.async 3-stage pipeline.
// Block tile 128x128x32, 8 warps, warp tile 32x64 (2x8 m16n8k8 frags).
// M % 128 == 0, K % 32 == 0. N guarded.  flags: bit0 = relu
// ---------------------------------------------------------------------------
struct GemmDesc { const float* A; const float* B; float* C; int N; int flags; };
struct GemmArgs { GemmDesc d[4]; };

#define BM 128
#define BN 128
#define BK 32
#define STR 36
#define A_STG (BM*STR)   // 4608 floats per stage
#define B_STG (BN*STR)   // 4608 floats per stage
#define GEMM_SMEM (3*(A_STG + B_STG)*4)   // 110592 bytes

__global__ __launch_bounds__(256, 2)
void gemm_mma(GemmArgs args, int K)
{
    GemmDesc g = args.d[blockIdx.z];
    const int bn = blockIdx.x * BN;
    if (bn >= g.N) return;
    const int bm = blockIdx.y * BM;

    extern __shared__ float sm[];
    float* As = sm;                // 3 stages
    float* Bs = sm + 3 * A_STG;    // 3 stages

    const int tid  = threadIdx.x;
    const int lane = tid & 31;
    const int warp = tid >> 5;
    const int wm   = warp >> 1;   // 0..3 -> 32 rows each
    const int wn   = warp & 1;    // 0..1 -> 64 cols each
    const int gid  = lane >> 2;   // 0..7
    const int quad = lane & 3;    // 0..3

    const int NT = K / BK;        // 16

    auto load_stage = [&](int s, int k0) {
        float* a = As + s * A_STG;
#pragma unroll
        for (int i = 0; i < 4; i++) {
            int id = tid + i * 256;
            int r  = id >> 3;
            int c  = (id & 7) * 4;
            cp16(a + r * STR + c, g.A + (size_t)(bm + r) * K + k0 + c, true);
        }
        float* b = Bs + s * B_STG;
#pragma unroll
        for (int i = 0; i < 4; i++) {
            int id = tid + i * 256;
            int r  = id >> 3;
            int c  = (id & 7) * 4;
            bool ok = (bn + r) < g.N;
            const float* src = ok ? (g.B + (size_t)(bn + r) * K + k0 + c) : g.B;
            cp16(b + r * STR + c, src, ok);
        }
        cp_commit();
    };

    float acc[2][8][4];
#pragma unroll
    for (int mt = 0; mt < 2; mt++)
#pragma unroll
        for (int nt = 0; nt < 8; nt++)
#pragma unroll
            for (int i = 0; i < 4; i++) acc[mt][nt][i] = 0.f;

    load_stage(0, 0);
    load_stage(1, BK);

    for (int kt = 0; kt < NT; kt++) {
        if (kt == NT - 1)
            asm volatile("cp.async.wait_group 0;");
        else
            asm volatile("cp.async.wait_group 1;");
        __syncthreads();

        if (kt + 2 < NT)
            load_stage((kt + 2) % 3, (kt + 2) * BK);

        const float* Af = As + (kt % 3) * A_STG;
        const float* Bf = Bs + (kt % 3) * B_STG;

#pragma unroll
        for (int kk = 0; kk < BK; kk += 8) {
            unsigned a[2][4], b[8][2];
#pragma unroll
            for (int mt = 0; mt < 2; mt++) {
                int r = wm * 32 + mt * 16 + gid;
                int c = kk + quad;
                a[mt][0] = f2tf(Af[r * STR + c]);
                a[mt][1] = f2tf(Af[(r + 8) * STR + c]);
                a[mt][2] = f2tf(Af[r * STR + c + 4]);
                a[mt][3] = f2tf(Af[(r + 8) * STR + c + 4]);
            }
#pragma unroll
            for (int nt = 0; nt < 8; nt++) {
                int n = wn * 64 + nt * 8 + gid;
                int c = kk + quad;
                b[nt][0] = f2tf(Bf[n * STR + c]);
                b[nt][1] = f2tf(Bf[n * STR + c + 4]);
            }
#pragma unroll
            for (int mt = 0; mt < 2; mt++)
#pragma unroll
                for (int nt = 0; nt < 8; nt++)
                    mma_tf32(acc[mt][nt], a[mt][0], a[mt][1], a[mt][2], a[mt][3],
                             b[nt][0], b[nt][1]);
        }
        __syncthreads();
    }

    const int relu = g.flags & 1;
#pragma unroll
    for (int mt = 0; mt < 2; mt++) {
        int r0 = bm + wm * 32 + mt * 16 + gid;
#pragma unroll
        for (int nt = 0; nt < 8; nt++) {
            int c0 = bn + wn * 64 + nt * 8 + quad * 2;
            float v0 = acc[mt][nt][0], v1 = acc[mt][nt][1];
            float v2 = acc[mt][nt][2], v3 = acc[mt][nt][3];
            if (relu) {
                v0 = fmaxf(v0, 0.f); v1 = fmaxf(v1, 0.f);
                v2 = fmaxf(v2, 0.f); v3 = fmaxf(v3, 0.f);
            }
            if (c0 < g.N) {
                g.C[(size_t)r0 * g.N + c0]       = v0;
                g.C[(size_t)(r0 + 8) * g.N + c0] = v2;
            }
            if (c0 + 1 < g.N) {
                g.C[(size_t)r0 * g.N + c0 + 1]       = v1;
                g.C[(size_t)(r0 + 8) * g.N + c0 + 1] = v3;
            }
        }
    }
}

// ---------------------------------------------------------------------------
// Windowed attention apply + fused softmax + scale mix.
// TCH tokens per block, 512 threads. Softmax done warp-per-row in smem.
// ---------------------------------------------------------------------------
__global__ __launch_bounds__(512)
void window_k(const float* __restrict__ sw_in)
{
    __shared__ float sa0[TCH][HS * CS0];
    __shared__ float sa1[TCH][HS * CS1];
    __shared__ float ssw[2];

    int t0g = blockIdx.x * TCH;      // global bt start (TCH divides TT)
    int b   = t0g / TT;
    int t0  = t0g - b * TT;
    int f   = threadIdx.x;

    // stage raw logits
    for (int i = f; i < TCH * HS * CS0; i += 512)
        ((float*)sa0)[i] = g_attn0[(size_t)t0g * (HS * CS0) + i];
    for (int i = f; i < TCH * HS * CS1; i += 512)
        ((float*)sa1)[i] = g_attn1[(size_t)t0g * (HS * CS1) + i];
    if (f == 0) {
        float a = sw_in[0], c = sw_in[1];
        float mx = fmaxf(a, c);
        float ea = __expf(a - mx), ec = __expf(c - mx);
        float inv = 1.f / (ea + ec);
        ssw[0] = ea * inv;
        ssw[1] = ec * inv;
    }
    __syncthreads();

    // fused softmax: warp-per-row, rows = TCH*HS = 64 per scale, 16 warps
    {
        int warp = f >> 5;
        int lane = f & 31;
#pragma unroll
        for (int scale = 0; scale < 2; scale++) {
            int cs = scale ? CS1 : CS0;
            float* base = scale ? &sa1[0][0] : &sa0[0][0];
            for (int r = warp; r < TCH * HS; r += 16) {
                float* p = base + r * cs;
                float v0 = (lane      < cs) ? p[lane]      : -INFINITY;
                float v1 = (lane + 32 < cs) ? p[lane + 32] : -INFINITY;
                float m = fmaxf(v0, v1);
#pragma unroll
                for (int o = 16; o > 0; o >>= 1)
                    m = fmaxf(m, __shfl_xor_sync(0xFFFFFFFFu, m, o));
                float e0 = (lane      < cs) ? __expf(v0 - m) : 0.f;
                float e1 = (lane + 32 < cs) ? __expf(v1 - m) : 0.f;
                float s = e0 + e1;
#pragma unroll
                for (int o = 16; o > 0; o >>= 1)
                    s += __shfl_xor_sync(0xFFFFFFFFu, s, o);
                float inv = 1.f / s;
                if (lane      < cs) p[lane]      = e0 * inv;
                if (lane + 32 < cs) p[lane + 32] = e1 * inv;
            }
        }
    }
    __syncthreads();

    int h = f >> 7;
    const float* v0b = g_v0 + ((size_t)b * TT) * FF + f;
    const float* v1b = g_v1 + ((size_t)b * TT) * FF + f;

    float acc0[TCH], acc1[TCH];
#pragma unroll
    for (int j = 0; j < TCH; j++) { acc0[j] = 0.f; acc1[j] = 0.f; }

    for (int r = 0; r < TCH - 1 + CS0; r++) {
        int tp = t0 + r - HALF0;
        float v = ((unsigned)tp < (unsigned)TT) ? v0b[(size_t)tp * FF] : 0.f;
#pragma unroll
        for (int j = 0; j < TCH; j++) {
            int c = r - j;
            if ((unsigned)c < (unsigned)CS0)
                acc0[j] = fmaf(sa0[j][h * CS0 + c], v, acc0[j]);
        }
    }
    for (int r = 0; r < TCH - 1 + CS1; r++) {
        int tp = t0 + r - HALF1;
        float v = ((unsigned)tp < (unsigned)TT) ? v1b[(size_t)tp * FF] : 0.f;
#pragma unroll
        for (int j = 0; j < TCH; j++) {
            int c = r - j;
            if ((unsigned)c < (unsigned)CS1)
                acc1[j] = fmaf(sa1[j][h * CS1 + c], v, acc1[j]);
        }
    }

    float s0 = ssw[0], s1 = ssw[1];
#pragma unroll
    for (int j = 0; j < TCH; j++)
        g_mix[(size_t)(t0g + j) * FF + f] = s0 * acc0[j] + s1 * acc1[j];
}

// ---------------------------------------------------------------------------
extern "C" void kernel_launch(void* const* d_in, const int* in_sizes, int n_in,
                              void* d_out, int out_size)
{
    const float* query = (const float*)d_in[0];
    // d_in[1] = key (unused by reference)
    const float* value = (const float*)d_in[2];
    const float* w1_0  = (const float*)d_in[3];
    const float* w1_1  = (const float*)d_in[4];
    const float* w2_0  = (const float*)d_in[5];
    const float* w2_1  = (const float*)d_in[6];
    const float* w3_0  = (const float*)d_in[7];
    const float* w3_1  = (const float*)d_in[8];
    const float* sw    = (const float*)d_in[9];
    const float* w_out = (const float*)d_in[10];
    float* out = (float*)d_out;

    float *rq0, *rq1, *v0, *v1, *mix, *a0, *a1;
    cudaGetSymbolAddress((void**)&rq0, g_rq0);
    cudaGetSymbolAddress((void**)&rq1, g_rq1);
    cudaGetSymbolAddress((void**)&v0,  g_v0);
    cudaGetSymbolAddress((void**)&v1,  g_v1);
    cudaGetSymbolAddress((void**)&mix, g_mix);
    cudaGetSymbolAddress((void**)&a0,  g_attn0);
    cudaGetSymbolAddress((void**)&a1,  g_attn1);

    static bool attr_done = false;
    if (!attr_done) {
        cudaFuncSetAttribute(gemm_mma, cudaFuncAttributeMaxDynamicSharedMemorySize,
                             GEMM_SMEM);
        attr_done = true;
    }

    // 1) 4 big GEMMs in one launch: q=relu(query@w1^T), v=value@w3^T
    GemmArgs gb;
    gb.d[0] = {query, w1_0, rq0, FF, 1};
    gb.d[1] = {query, w1_1, rq1, FF, 1};
    gb.d[2] = {value, w3_0, v0,  FF, 0};
    gb.d[3] = {value, w3_1, v1,  FF, 0};
    gemm_mma<<<dim3(FF / BN, BT / BM, 4), 256, GEMM_SMEM>>>(gb, FF);

    // 2) logits GEMMs (raw logits; softmax fused into window_k)
    GemmArgs gl;
    gl.d[0] = {rq0, w2_0, a0, HS * CS0, 0};
    gl.d[1] = {rq1, w2_1, a1, HS * CS1, 0};
    gl.d[2] = gl.d[0]; gl.d[3] = gl.d[0];
    gemm_mma<<<dim3((HS * CS1 + BN - 1) / BN, BT / BM, 2), 256, GEMM_SMEM>>>(gl, FF);

    // 3) fused softmax + window apply + scale mixing
    window_k<<<BT / TCH, 512>>>(sw);

    // 4) final projection
    GemmArgs gf;
    gf.d[0] = {mix, w_out, out, FF, 0};
    gf.d[1] = gf.d[0]; gf.d[2] = gf.d[0]; gf.d[3] = gf.d[0];
    gemm_mma<<<dim3(FF / BN, BT / BM, 1), 256, GEMM_SMEM>>>(gf, FF);
}

// round 5
// speedup vs baseline: 2.7880x; 1.0193x over previous
#include <cuda_runtime.h>
#include <math.h>
#include <stdint.h>

// Problem constants
#define BB 4
#define TT 2048
#define BT (BB*TT)     // 8192
#define FF 512
#define HS 4
#define CS0 31
#define CS1 61
#define HALF0 15
#define HALF1 30
#define TCH 16         // tokens per window block

#define W_SZ (FF*FF)
#define W2_0_SZ (HS*CS0*FF)
#define W2_1_SZ (HS*CS1*FF)
#define OFF_W1_0 0
#define OFF_W1_1 (W_SZ)
#define OFF_W3_0 (2*W_SZ)
#define OFF_W3_1 (3*W_SZ)
#define OFF_WOUT (4*W_SZ)
#define OFF_W2_0 (5*W_SZ)
#define OFF_W2_1 (5*W_SZ + W2_0_SZ)
#define WTF_TOTAL (5*W_SZ + W2_0_SZ + W2_1_SZ)

// Scratch (device globals: alloc-free rule)
__device__ float g_qtf[BT*FF];
__device__ float g_vtf[BT*FF];
__device__ float g_wtf[WTF_TOTAL];
__device__ float g_rq0[BT*FF];
__device__ float g_rq1[BT*FF];
__device__ float g_v0 [BT*FF];
__device__ float g_v1 [BT*FF];
__device__ float g_mix[BT*FF];
__device__ float g_attn0[BT*HS*CS0];   // raw logits, softmaxed in window_k
__device__ float g_attn1[BT*HS*CS1];

__device__ __forceinline__ unsigned f2tf(float x) {
    unsigned r;
    asm("cvt.rna.tf32.f32 %0, %1;" : "=r"(r) : "f"(x));
    return r;
}
__device__ __forceinline__ float f2tf_f(float x) {
    return __uint_as_float(f2tf(x));
}

__device__ __forceinline__ void mma_tf32(float c[4], unsigned a0, unsigned a1,
                                         unsigned a2, unsigned a3,
                                         unsigned b0, unsigned b1) {
    asm volatile(
        "mma.sync.aligned.m16n8k8.row.col.f32.tf32.tf32.f32 "
        "{%0,%1,%2,%3}, {%4,%5,%6,%7}, {%8,%9}, {%0,%1,%2,%3};"
        : "+f"(c[0]), "+f"(c[1]), "+f"(c[2]), "+f"(c[3])
        : "r"(a0), "r"(a1), "r"(a2), "r"(a3), "r"(b0), "r"(b1));
}

__device__ __forceinline__ void cp16(float* dst_smem, const float* src, bool pred) {
    unsigned d = (unsigned)__cvta_generic_to_shared(dst_smem);
    int sz = pred ? 16 : 0;
    asm volatile("cp.async.cg.shared.global [%0], [%1], 16, %2;"
                 :: "r"(d), "l"(src), "r"(sz));
}
__device__ __forceinline__ void cp_commit() {
    asm volatile("cp.async.commit_group;");
}

// ---------------------------------------------------------------------------
// tf32 rna-rounding prepass (inputs + weights only; cheap)
// ---------------------------------------------------------------------------
struct RDesc { const float* s; float* d; int n4; };
struct RArgs { RDesc r[9]; };

__global__ void round_k(RArgs a)
{
    RDesc t = a.r[blockIdx.z];
    int stride = gridDim.x * blockDim.x;
    for (int i = blockIdx.x * blockDim.x + threadIdx.x; i < t.n4; i += stride) {
        float4 v = ((const float4*)t.s)[i];
        ((uint4*)t.d)[i] = make_uint4(f2tf(v.x), f2tf(v.y), f2tf(v.z), f2tf(v.w));
    }
}

// ---------------------------------------------------------------------------
// Batched tf32 GEMM: C[M,N] = act( A[M,K] @ B[N,K]^T ).
// Inputs already tf32-rounded (raw bits). No cvt in mainloop.
// cp.async 3-stage. Block 128x128x32, 8 warps, warp tile 32x64.
// flags: bit0 = relu, bit1 = round output to tf32
// ---------------------------------------------------------------------------
struct GemmDesc { const float* A; const float* B; float* C; int N; int flags; };
struct GemmArgs { GemmDesc d[4]; };

#define BM 128
#define BN 128
#define BK 32
#define STR 36
#define A_STG (BM*STR)
#define B_STG (BN*STR)
#define GEMM_SMEM (3*(A_STG + B_STG)*4)   // 110592 bytes

__global__ __launch_bounds__(256, 2)
void gemm_mma(GemmArgs args, int K)
{
    GemmDesc g = args.d[blockIdx.z];
    const int bn = blockIdx.x * BN;
    if (bn >= g.N) return;
    const int bm = blockIdx.y * BM;

    extern __shared__ float sm[];
    float* As = sm;
    float* Bs = sm + 3 * A_STG;

    const int tid  = threadIdx.x;
    const int lane = tid & 31;
    const int warp = tid >> 5;
    const int wm   = warp >> 1;
    const int wn   = warp & 1;
    const int gid  = lane >> 2;
    const int quad = lane & 3;

    const int NT = K / BK;

    auto load_stage = [&](int s, int k0) {
        float* a = As + s * A_STG;
#pragma unroll
        for (int i = 0; i < 4; i++) {
            int id = tid + i * 256;
            int r  = id >> 3;
            int c  = (id & 7) * 4;
            cp16(a + r * STR + c, g.A + (size_t)(bm + r) * K + k0 + c, true);
        }
        float* b = Bs + s * B_STG;
#pragma unroll
        for (int i = 0; i < 4; i++) {
            int id = tid + i * 256;
            int r  = id >> 3;
            int c  = (id & 7) * 4;
            bool ok = (bn + r) < g.N;
            const float* src = ok ? (g.B + (size_t)(bn + r) * K + k0 + c) : g.B;
            cp16(b + r * STR + c, src, ok);
        }
        cp_commit();
    };

    float acc[2][8][4];
#pragma unroll
    for (int mt = 0; mt < 2; mt++)
#pragma unroll
        for (int nt = 0; nt < 8; nt++)
#pragma unroll
            for (int i = 0; i < 4; i++) acc[mt][nt][i] = 0.f;

    load_stage(0, 0);
    load_stage(1, BK);

    for (int kt = 0; kt < NT; kt++) {
        if (kt == NT - 1)
            asm volatile("cp.async.wait_group 0;");
        else
            asm volatile("cp.async.wait_group 1;");
        __syncthreads();

        if (kt + 2 < NT)
            load_stage((kt + 2) % 3, (kt + 2) * BK);

        const unsigned* Au = (const unsigned*)(As + (kt % 3) * A_STG);
        const unsigned* Bu = (const unsigned*)(Bs + (kt % 3) * B_STG);

#pragma unroll
        for (int kk = 0; kk < BK; kk += 8) {
            unsigned a[2][4], b[8][2];
#pragma unroll
            for (int mt = 0; mt < 2; mt++) {
                int r = wm * 32 + mt * 16 + gid;
                int c = kk + quad;
                a[mt][0] = Au[r * STR + c];
                a[mt][1] = Au[(r + 8) * STR + c];
                a[mt][2] = Au[r * STR + c + 4];
                a[mt][3] = Au[(r + 8) * STR + c + 4];
            }
#pragma unroll
            for (int nt = 0; nt < 8; nt++) {
                int n = wn * 64 + nt * 8 + gid;
                int c = kk + quad;
                b[nt][0] = Bu[n * STR + c];
                b[nt][1] = Bu[n * STR + c + 4];
            }
#pragma unroll
            for (int mt = 0; mt < 2; mt++)
#pragma unroll
                for (int nt = 0; nt < 8; nt++)
                    mma_tf32(acc[mt][nt], a[mt][0], a[mt][1], a[mt][2], a[mt][3],
                             b[nt][0], b[nt][1]);
        }
        __syncthreads();
    }

    const int relu = g.flags & 1;
    const int rnd  = g.flags & 2;
#pragma unroll
    for (int mt = 0; mt < 2; mt++) {
        int r0 = bm + wm * 32 + mt * 16 + gid;
#pragma unroll
        for (int nt = 0; nt < 8; nt++) {
            int c0 = bn + wn * 64 + nt * 8 + quad * 2;
            float v0 = acc[mt][nt][0], v1 = acc[mt][nt][1];
            float v2 = acc[mt][nt][2], v3 = acc[mt][nt][3];
            if (relu) {
                v0 = fmaxf(v0, 0.f); v1 = fmaxf(v1, 0.f);
                v2 = fmaxf(v2, 0.f); v3 = fmaxf(v3, 0.f);
            }
            if (rnd) {
                v0 = f2tf_f(v0); v1 = f2tf_f(v1);
                v2 = f2tf_f(v2); v3 = f2tf_f(v3);
            }
            if (c0 < g.N) {
                g.C[(size_t)r0 * g.N + c0]       = v0;
                g.C[(size_t)(r0 + 8) * g.N + c0] = v2;
            }
            if (c0 + 1 < g.N) {
                g.C[(size_t)r0 * g.N + c0 + 1]       = v1;
                g.C[(size_t)(r0 + 8) * g.N + c0 + 1] = v3;
            }
        }
    }
}

// ---------------------------------------------------------------------------
// Windowed attention apply + fused softmax + scale mix.
// Output mix rounded to tf32 (A of final GEMM).
// ---------------------------------------------------------------------------
__global__ __launch_bounds__(512)
void window_k(const float* __restrict__ sw_in)
{
    __shared__ float sa0[TCH][HS * CS0];
    __shared__ float sa1[TCH][HS * CS1];
    __shared__ float ssw[2];

    int t0g = blockIdx.x * TCH;
    int b   = t0g / TT;
    int t0  = t0g - b * TT;
    int f   = threadIdx.x;

    for (int i = f; i < TCH * HS * CS0; i += 512)
        ((float*)sa0)[i] = g_attn0[(size_t)t0g * (HS * CS0) + i];
    for (int i = f; i < TCH * HS * CS1; i += 512)
        ((float*)sa1)[i] = g_attn1[(size_t)t0g * (HS * CS1) + i];
    if (f == 0) {
        float a = sw_in[0], c = sw_in[1];
        float mx = fmaxf(a, c);
        float ea = __expf(a - mx), ec = __expf(c - mx);
        float inv = 1.f / (ea + ec);
        ssw[0] = ea * inv;
        ssw[1] = ec * inv;
    }
    __syncthreads();

    // fused softmax: warp-per-row
    {
        int warp = f >> 5;
        int lane = f & 31;
#pragma unroll
        for (int scale = 0; scale < 2; scale++) {
            int cs = scale ? CS1 : CS0;
            float* base = scale ? &sa1[0][0] : &sa0[0][0];
            for (int r = warp; r < TCH * HS; r += 16) {
                float* p = base + r * cs;
                float v0 = (lane      < cs) ? p[lane]      : -INFINITY;
                float v1 = (lane + 32 < cs) ? p[lane + 32] : -INFINITY;
                float m = fmaxf(v0, v1);
#pragma unroll
                for (int o = 16; o > 0; o >>= 1)
                    m = fmaxf(m, __shfl_xor_sync(0xFFFFFFFFu, m, o));
                float e0 = (lane      < cs) ? __expf(v0 - m) : 0.f;
                float e1 = (lane + 32 < cs) ? __expf(v1 - m) : 0.f;
                float s = e0 + e1;
#pragma unroll
                for (int o = 16; o > 0; o >>= 1)
                    s += __shfl_xor_sync(0xFFFFFFFFu, s, o);
                float inv = 1.f / s;
                if (lane      < cs) p[lane]      = e0 * inv;
                if (lane + 32 < cs) p[lane + 32] = e1 * inv;
            }
        }
    }
    __syncthreads();

    int h = f >> 7;
    const float* v0b = g_v0 + ((size_t)b * TT) * FF + f;
    const float* v1b = g_v1 + ((size_t)b * TT) * FF + f;

    float acc0[TCH], acc1[TCH];
#pragma unroll
    for (int j = 0; j < TCH; j++) { acc0[j] = 0.f; acc1[j] = 0.f; }

    for (int r = 0; r < TCH - 1 + CS0; r++) {
        int tp = t0 + r - HALF0;
        float v = ((unsigned)tp < (unsigned)TT) ? v0b[(size_t)tp * FF] : 0.f;
#pragma unroll
        for (int j = 0; j < TCH; j++) {
            int c = r - j;
            if ((unsigned)c < (unsigned)CS0)
                acc0[j] = fmaf(sa0[j][h * CS0 + c], v, acc0[j]);
        }
    }
    for (int r = 0; r < TCH - 1 + CS1; r++) {
        int tp = t0 + r - HALF1;
        float v = ((unsigned)tp < (unsigned)TT) ? v1b[(size_t)tp * FF] : 0.f;
#pragma unroll
        for (int j = 0; j < TCH; j++) {
            int c = r - j;
            if ((unsigned)c < (unsigned)CS1)
                acc1[j] = fmaf(sa1[j][h * CS1 + c], v, acc1[j]);
        }
    }

    float s0 = ssw[0], s1 = ssw[1];
#pragma unroll
    for (int j = 0; j < TCH; j++)
        g_mix[(size_t)(t0g + j) * FF + f] = f2tf_f(s0 * acc0[j] + s1 * acc1[j]);
}

// ---------------------------------------------------------------------------
extern "C" void kernel_launch(void* const* d_in, const int* in_sizes, int n_in,
                              void* d_out, int out_size)
{
    const float* query = (const float*)d_in[0];
    // d_in[1] = key (unused by reference)
    const float* value = (const float*)d_in[2];
    const float* w1_0  = (const float*)d_in[3];
    const float* w1_1  = (const float*)d_in[4];
    const float* w2_0  = (const float*)d_in[5];
    const float* w2_1  = (const float*)d_in[6];
    const float* w3_0  = (const float*)d_in[7];
    const float* w3_1  = (const float*)d_in[8];
    const float* sw    = (const float*)d_in[9];
    const float* w_out = (const float*)d_in[10];
    float* out = (float*)d_out;

    float *qtf, *vtf, *wtf, *rq0, *rq1, *v0, *v1, *mix, *a0, *a1;
    cudaGetSymbolAddress((void**)&qtf, g_qtf);
    cudaGetSymbolAddress((void**)&vtf, g_vtf);
    cudaGetSymbolAddress((void**)&wtf, g_wtf);
    cudaGetSymbolAddress((void**)&rq0, g_rq0);
    cudaGetSymbolAddress((void**)&rq1, g_rq1);
    cudaGetSymbolAddress((void**)&v0,  g_v0);
    cudaGetSymbolAddress((void**)&v1,  g_v1);
    cudaGetSymbolAddress((void**)&mix, g_mix);
    cudaGetSymbolAddress((void**)&a0,  g_attn0);
    cudaGetSymbolAddress((void**)&a1,  g_attn1);

    static bool attr_done = false;
    if (!attr_done) {
        cudaFuncSetAttribute(gemm_mma, cudaFuncAttributeMaxDynamicSharedMemorySize,
                             GEMM_SMEM);
        attr_done = true;
    }

    // 1) tf32 rounding prepass (inputs + weights)
    RArgs ra;
    ra.r[0] = {query, qtf, BT * FF / 4};
    ra.r[1] = {value, vtf, BT * FF / 4};
    ra.r[2] = {w1_0, wtf + OFF_W1_0, W_SZ / 4};
    ra.r[3] = {w1_1, wtf + OFF_W1_1, W_SZ / 4};
    ra.r[4] = {w3_0, wtf + OFF_W3_0, W_SZ / 4};
    ra.r[5] = {w3_1, wtf + OFF_W3_1, W_SZ / 4};
    ra.r[6] = {w_out, wtf + OFF_WOUT, W_SZ / 4};
    ra.r[7] = {w2_0, wtf + OFF_W2_0, W2_0_SZ / 4};
    ra.r[8] = {w2_1, wtf + OFF_W2_1, W2_1_SZ / 4};
    round_k<<<dim3(192, 1, 9), 256>>>(ra);

    // 2) 4 big GEMMs: q=relu(query@w1^T) [rounded], v=value@w3^T [raw fp32 out]
    GemmArgs gb;
    gb.d[0] = {qtf, wtf + OFF_W1_0, rq0, FF, 1 | 2};
    gb.d[1] = {qtf, wtf + OFF_W1_1, rq1, FF, 1 | 2};
    gb.d[2] = {vtf, wtf + OFF_W3_0, v0,  FF, 0};
    gb.d[3] = {vtf, wtf + OFF_W3_1, v1,  FF, 0};
    gemm_mma<<<dim3(FF / BN, BT / BM, 4), 256, GEMM_SMEM>>>(gb, FF);

    // 3) logits GEMMs (raw logits; softmax fused into window_k)
    GemmArgs gl;
    gl.d[0] = {rq0, wtf + OFF_W2_0, a0, HS * CS0, 0};
    gl.d[1] = {rq1, wtf + OFF_W2_1, a1, HS * CS1, 0};
    gl.d[2] = gl.d[0]; gl.d[3] = gl.d[0];
    gemm_mma<<<dim3((HS * CS1 + BN - 1) / BN, BT / BM, 2), 256, GEMM_SMEM>>>(gl, FF);

    // 4) fused softmax + window apply + scale mixing (mix rounded to tf32)
    window_k<<<BT / TCH, 512>>>(sw);

    // 5) final projection
    GemmArgs gf;
    gf.d[0] = {mix, wtf + OFF_WOUT, out, FF, 0};
    gf.d[1] = gf.d[0]; gf.d[2] = gf.d[0]; gf.d[3] = gf.d[0];
    gemm_mma<<<dim3(FF / BN, BT / BM, 1), 256, GEMM_SMEM>>>(gf, FF);
}

// round 6
// speedup vs baseline: 3.2404x; 1.1623x over previous
#include <cuda_runtime.h>
#include <math.h>
#include <stdint.h>

// Problem constants
#define BB 4
#define TT 2048
#define BT (BB*TT)     // 8192
#define FF 512
#define HS 4
#define CS0 31
#define CS1 61
#define HALF0 15
#define HALF1 30
#define TCH 16         // tokens per window block

#define W_SZ (FF*FF)
#define W2_0_SZ (HS*CS0*FF)
#define W2_1_SZ (HS*CS1*FF)
#define OFF_W1_0 0
#define OFF_W1_1 (W_SZ)
#define OFF_W3_0 (2*W_SZ)
#define OFF_W3_1 (3*W_SZ)
#define OFF_WOUT (4*W_SZ)
#define OFF_W2_0 (5*W_SZ)
#define OFF_W2_1 (5*W_SZ + W2_0_SZ)
#define WTF_TOTAL (5*W_SZ + W2_0_SZ + W2_1_SZ)

// Scratch (device globals: alloc-free rule)
__device__ float g_qtf[BT*FF];
__device__ float g_vtf[BT*FF];
__device__ float g_wtf[WTF_TOTAL];
__device__ float g_rq0[BT*FF];
__device__ float g_rq1[BT*FF];
__device__ float g_v0 [BT*FF];
__device__ float g_v1 [BT*FF];
__device__ float g_mix[BT*FF];
__device__ float g_attn0[BT*HS*CS0];   // raw logits, softmaxed in window_k
__device__ float g_attn1[BT*HS*CS1];

__device__ __forceinline__ unsigned f2tf(float x) {
    unsigned r;
    asm("cvt.rna.tf32.f32 %0, %1;" : "=r"(r) : "f"(x));
    return r;
}
__device__ __forceinline__ float f2tf_f(float x) {
    return __uint_as_float(f2tf(x));
}

__device__ __forceinline__ void mma_tf32(float c[4], unsigned a0, unsigned a1,
                                         unsigned a2, unsigned a3,
                                         unsigned b0, unsigned b1) {
    asm volatile(
        "mma.sync.aligned.m16n8k8.row.col.f32.tf32.tf32.f32 "
        "{%0,%1,%2,%3}, {%4,%5,%6,%7}, {%8,%9}, {%0,%1,%2,%3};"
        : "+f"(c[0]), "+f"(c[1]), "+f"(c[2]), "+f"(c[3])
        : "r"(a0), "r"(a1), "r"(a2), "r"(a3), "r"(b0), "r"(b1));
}

__device__ __forceinline__ void cp16(float* dst_smem, const float* src, bool pred) {
    unsigned d = (unsigned)__cvta_generic_to_shared(dst_smem);
    int sz = pred ? 16 : 0;
    asm volatile("cp.async.cg.shared.global [%0], [%1], 16, %2;"
                 :: "r"(d), "l"(src), "r"(sz));
}
__device__ __forceinline__ void cp_commit() {
    asm volatile("cp.async.commit_group;");
}

// ---------------------------------------------------------------------------
// tf32 rna-rounding prepass (inputs + weights only; cheap)
// ---------------------------------------------------------------------------
struct RDesc { const float* s; float* d; int n4; };
struct RArgs { RDesc r[9]; };

__global__ void round_k(RArgs a)
{
    RDesc t = a.r[blockIdx.z];
    int stride = gridDim.x * blockDim.x;
    for (int i = blockIdx.x * blockDim.x + threadIdx.x; i < t.n4; i += stride) {
        float4 v = ((const float4*)t.s)[i];
        ((uint4*)t.d)[i] = make_uint4(f2tf(v.x), f2tf(v.y), f2tf(v.z), f2tf(v.w));
    }
}

// ---------------------------------------------------------------------------
// Batched tf32 GEMM: C[M,N] = act( A[M,K] @ B[N,K]^T ).
// Inputs already tf32-rounded (raw bits). No cvt in mainloop.
// cp.async 3-stage. Block 128x128x32, 8 warps, warp tile 32x64.
// flags: bit0 = relu, bit1 = round output to tf32
// ---------------------------------------------------------------------------
struct GemmDesc { const float* A; const float* B; float* C; int N; int flags; };
struct GemmArgs { GemmDesc d[4]; };

#define BM 128
#define BN 128
#define BK 32
#define STR 36
#define A_STG (BM*STR)
#define B_STG (BN*STR)
#define GEMM_SMEM (3*(A_STG + B_STG)*4)   // 110592 bytes

__global__ __launch_bounds__(256, 2)
void gemm_mma(GemmArgs args, int K)
{
    GemmDesc g = args.d[blockIdx.z];
    const int bn = blockIdx.x * BN;
    if (bn >= g.N) return;
    const int bm = blockIdx.y * BM;

    extern __shared__ float sm[];
    float* As = sm;
    float* Bs = sm + 3 * A_STG;

    const int tid  = threadIdx.x;
    const int lane = tid & 31;
    const int warp = tid >> 5;
    const int wm   = warp >> 1;
    const int wn   = warp & 1;
    const int gid  = lane >> 2;
    const int quad = lane & 3;

    const int NT = K / BK;

    auto load_stage = [&](int s, int k0) {
        float* a = As + s * A_STG;
#pragma unroll
        for (int i = 0; i < 4; i++) {
            int id = tid + i * 256;
            int r  = id >> 3;
            int c  = (id & 7) * 4;
            cp16(a + r * STR + c, g.A + (size_t)(bm + r) * K + k0 + c, true);
        }
        float* b = Bs + s * B_STG;
#pragma unroll
        for (int i = 0; i < 4; i++) {
            int id = tid + i * 256;
            int r  = id >> 3;
            int c  = (id & 7) * 4;
            bool ok = (bn + r) < g.N;
            const float* src = ok ? (g.B + (size_t)(bn + r) * K + k0 + c) : g.B;
            cp16(b + r * STR + c, src, ok);
        }
        cp_commit();
    };

    float acc[2][8][4];
#pragma unroll
    for (int mt = 0; mt < 2; mt++)
#pragma unroll
        for (int nt = 0; nt < 8; nt++)
#pragma unroll
            for (int i = 0; i < 4; i++) acc[mt][nt][i] = 0.f;

    load_stage(0, 0);
    load_stage(1, BK);

    for (int kt = 0; kt < NT; kt++) {
        if (kt == NT - 1)
            asm volatile("cp.async.wait_group 0;");
        else
            asm volatile("cp.async.wait_group 1;");
        __syncthreads();

        if (kt + 2 < NT)
            load_stage((kt + 2) % 3, (kt + 2) * BK);

        const unsigned* Au = (const unsigned*)(As + (kt % 3) * A_STG);
        const unsigned* Bu = (const unsigned*)(Bs + (kt % 3) * B_STG);

#pragma unroll
        for (int kk = 0; kk < BK; kk += 8) {
            unsigned a[2][4], b[8][2];
#pragma unroll
            for (int mt = 0; mt < 2; mt++) {
                int r = wm * 32 + mt * 16 + gid;
                int c = kk + quad;
                a[mt][0] = Au[r * STR + c];
                a[mt][1] = Au[(r + 8) * STR + c];
                a[mt][2] = Au[r * STR + c + 4];
                a[mt][3] = Au[(r + 8) * STR + c + 4];
            }
#pragma unroll
            for (int nt = 0; nt < 8; nt++) {
                int n = wn * 64 + nt * 8 + gid;
                int c = kk + quad;
                b[nt][0] = Bu[n * STR + c];
                b[nt][1] = Bu[n * STR + c + 4];
            }
#pragma unroll
            for (int mt = 0; mt < 2; mt++)
#pragma unroll
                for (int nt = 0; nt < 8; nt++)
                    mma_tf32(acc[mt][nt], a[mt][0], a[mt][1], a[mt][2], a[mt][3],
                             b[nt][0], b[nt][1]);
        }
        __syncthreads();
    }

    const int relu = g.flags & 1;
    const int rnd  = g.flags & 2;
#pragma unroll
    for (int mt = 0; mt < 2; mt++) {
        int r0 = bm + wm * 32 + mt * 16 + gid;
#pragma unroll
        for (int nt = 0; nt < 8; nt++) {
            int c0 = bn + wn * 64 + nt * 8 + quad * 2;
            float v0 = acc[mt][nt][0], v1 = acc[mt][nt][1];
            float v2 = acc[mt][nt][2], v3 = acc[mt][nt][3];
            if (relu) {
                v0 = fmaxf(v0, 0.f); v1 = fmaxf(v1, 0.f);
                v2 = fmaxf(v2, 0.f); v3 = fmaxf(v3, 0.f);
            }
            if (rnd) {
                v0 = f2tf_f(v0); v1 = f2tf_f(v1);
                v2 = f2tf_f(v2); v3 = f2tf_f(v3);
            }
            if (c0 < g.N) {
                g.C[(size_t)r0 * g.N + c0]       = v0;
                g.C[(size_t)(r0 + 8) * g.N + c0] = v2;
            }
            if (c0 + 1 < g.N) {
                g.C[(size_t)r0 * g.N + c0 + 1]       = v1;
                g.C[(size_t)(r0 + 8) * g.N + c0 + 1] = v3;
            }
        }
    }
}

// ---------------------------------------------------------------------------
// Windowed attention apply + fused softmax + scale mix.
// FULLY UNROLLED r-loops: all (r-j) window predicates fold at compile time,
// leaving pure LDS+FFMA with immediate offsets. Only v boundary checks remain.
// Output mix rounded to tf32 (A of final GEMM).
// ---------------------------------------------------------------------------
__global__ __launch_bounds__(512)
void window_k(const float* __restrict__ sw_in)
{
    __shared__ float sa0[TCH][HS * CS0];
    __shared__ float sa1[TCH][HS * CS1];
    __shared__ float ssw[2];

    int t0g = blockIdx.x * TCH;
    int b   = t0g / TT;
    int t0  = t0g - b * TT;
    int f   = threadIdx.x;

    for (int i = f; i < TCH * HS * CS0; i += 512)
        ((float*)sa0)[i] = g_attn0[(size_t)t0g * (HS * CS0) + i];
    for (int i = f; i < TCH * HS * CS1; i += 512)
        ((float*)sa1)[i] = g_attn1[(size_t)t0g * (HS * CS1) + i];
    if (f == 0) {
        float a = sw_in[0], c = sw_in[1];
        float mx = fmaxf(a, c);
        float ea = __expf(a - mx), ec = __expf(c - mx);
        float inv = 1.f / (ea + ec);
        ssw[0] = ea * inv;
        ssw[1] = ec * inv;
    }
    __syncthreads();

    // fused softmax: warp-per-row
    {
        int warp = f >> 5;
        int lane = f & 31;
#pragma unroll
        for (int scale = 0; scale < 2; scale++) {
            int cs = scale ? CS1 : CS0;
            float* base = scale ? &sa1[0][0] : &sa0[0][0];
            for (int r = warp; r < TCH * HS; r += 16) {
                float* p = base + r * cs;
                float v0 = (lane      < cs) ? p[lane]      : -INFINITY;
                float v1 = (lane + 32 < cs) ? p[lane + 32] : -INFINITY;
                float m = fmaxf(v0, v1);
#pragma unroll
                for (int o = 16; o > 0; o >>= 1)
                    m = fmaxf(m, __shfl_xor_sync(0xFFFFFFFFu, m, o));
                float e0 = (lane      < cs) ? __expf(v0 - m) : 0.f;
                float e1 = (lane + 32 < cs) ? __expf(v1 - m) : 0.f;
                float s = e0 + e1;
#pragma unroll
                for (int o = 16; o > 0; o >>= 1)
                    s += __shfl_xor_sync(0xFFFFFFFFu, s, o);
                float inv = 1.f / s;
                if (lane      < cs) p[lane]      = e0 * inv;
                if (lane + 32 < cs) p[lane + 32] = e1 * inv;
            }
        }
    }
    __syncthreads();

    int h = f >> 7;
    const float* v0b = g_v0 + ((size_t)b * TT) * FF + f;
    const float* v1b = g_v1 + ((size_t)b * TT) * FF + f;
    const float* c0b = &sa0[0][0] + h * CS0;   // coeff base, head-offset
    const float* c1b = &sa1[0][0] + h * CS1;

    float acc0[TCH], acc1[TCH];
#pragma unroll
    for (int j = 0; j < TCH; j++) { acc0[j] = 0.f; acc1[j] = 0.f; }

#pragma unroll
    for (int r = 0; r < TCH - 1 + CS0; r++) {
        int tp = t0 + r - HALF0;
        float v = ((unsigned)tp < (unsigned)TT) ? v0b[(size_t)tp * FF] : 0.f;
#pragma unroll
        for (int j = 0; j < TCH; j++) {
            int c = r - j;
            if (c >= 0 && c < CS0)   // compile-time constant after full unroll
                acc0[j] = fmaf(c0b[j * (HS * CS0) + c], v, acc0[j]);
        }
    }
#pragma unroll
    for (int r = 0; r < TCH - 1 + CS1; r++) {
        int tp = t0 + r - HALF1;
        float v = ((unsigned)tp < (unsigned)TT) ? v1b[(size_t)tp * FF] : 0.f;
#pragma unroll
        for (int j = 0; j < TCH; j++) {
            int c = r - j;
            if (c >= 0 && c < CS1)   // compile-time constant after full unroll
                acc1[j] = fmaf(c1b[j * (HS * CS1) + c], v, acc1[j]);
        }
    }

    float s0 = ssw[0], s1 = ssw[1];
#pragma unroll
    for (int j = 0; j < TCH; j++)
        g_mix[(size_t)(t0g + j) * FF + f] = f2tf_f(s0 * acc0[j] + s1 * acc1[j]);
}

// ---------------------------------------------------------------------------
extern "C" void kernel_launch(void* const* d_in, const int* in_sizes, int n_in,
                              void* d_out, int out_size)
{
    const float* query = (const float*)d_in[0];
    // d_in[1] = key (unused by reference)
    const float* value = (const float*)d_in[2];
    const float* w1_0  = (const float*)d_in[3];
    const float* w1_1  = (const float*)d_in[4];
    const float* w2_0  = (const float*)d_in[5];
    const float* w2_1  = (const float*)d_in[6];
    const float* w3_0  = (const float*)d_in[7];
    const float* w3_1  = (const float*)d_in[8];
    const float* sw    = (const float*)d_in[9];
    const float* w_out = (const float*)d_in[10];
    float* out = (float*)d_out;

    float *qtf, *vtf, *wtf, *rq0, *rq1, *v0, *v1, *mix, *a0, *a1;
    cudaGetSymbolAddress((void**)&qtf, g_qtf);
    cudaGetSymbolAddress((void**)&vtf, g_vtf);
    cudaGetSymbolAddress((void**)&wtf, g_wtf);
    cudaGetSymbolAddress((void**)&rq0, g_rq0);
    cudaGetSymbolAddress((void**)&rq1, g_rq1);
    cudaGetSymbolAddress((void**)&v0,  g_v0);
    cudaGetSymbolAddress((void**)&v1,  g_v1);
    cudaGetSymbolAddress((void**)&mix, g_mix);
    cudaGetSymbolAddress((void**)&a0,  g_attn0);
    cudaGetSymbolAddress((void**)&a1,  g_attn1);

    static bool attr_done = false;
    if (!attr_done) {
        cudaFuncSetAttribute(gemm_mma, cudaFuncAttributeMaxDynamicSharedMemorySize,
                             GEMM_SMEM);
        attr_done = true;
    }

    // 1) tf32 rounding prepass (inputs + weights)
    RArgs ra;
    ra.r[0] = {query, qtf, BT * FF / 4};
    ra.r[1] = {value, vtf, BT * FF / 4};
    ra.r[2] = {w1_0, wtf + OFF_W1_0, W_SZ / 4};
    ra.r[3] = {w1_1, wtf + OFF_W1_1, W_SZ / 4};
    ra.r[4] = {w3_0, wtf + OFF_W3_0, W_SZ / 4};
    ra.r[5] = {w3_1, wtf + OFF_W3_1, W_SZ / 4};
    ra.r[6] = {w_out, wtf + OFF_WOUT, W_SZ / 4};
    ra.r[7] = {w2_0, wtf + OFF_W2_0, W2_0_SZ / 4};
    ra.r[8] = {w2_1, wtf + OFF_W2_1, W2_1_SZ / 4};
    round_k<<<dim3(192, 1, 9), 256>>>(ra);

    // 2) 4 big GEMMs: q=relu(query@w1^T) [rounded], v=value@w3^T [raw fp32 out]
    GemmArgs gb;
    gb.d[0] = {qtf, wtf + OFF_W1_0, rq0, FF, 1 | 2};
    gb.d[1] = {qtf, wtf + OFF_W1_1, rq1, FF, 1 | 2};
    gb.d[2] = {vtf, wtf + OFF_W3_0, v0,  FF, 0};
    gb.d[3] = {vtf, wtf + OFF_W3_1, v1,  FF, 0};
    gemm_mma<<<dim3(FF / BN, BT / BM, 4), 256, GEMM_SMEM>>>(gb, FF);

    // 3) logits GEMMs (raw logits; softmax fused into window_k)
    GemmArgs gl;
    gl.d[0] = {rq0, wtf + OFF_W2_0, a0, HS * CS0, 0};
    gl.d[1] = {rq1, wtf + OFF_W2_1, a1, HS * CS1, 0};
    gl.d[2] = gl.d[0]; gl.d[3] = gl.d[0];
    gemm_mma<<<dim3((HS * CS1 + BN - 1) / BN, BT / BM, 2), 256, GEMM_SMEM>>>(gl, FF);

    // 4) fused softmax + window apply + scale mixing (mix rounded to tf32)
    window_k<<<BT / TCH, 512>>>(sw);

    // 5) final projection
    GemmArgs gf;
    gf.d[0] = {mix, wtf + OFF_WOUT, out, FF, 0};
    gf.d[1] = gf.d[0]; gf.d[2] = gf.d[0]; gf.d[3] = gf.d[0];
    gemm_mma<<<dim3(FF / BN, BT / BM, 1), 256, GEMM_SMEM>>>(gf, FF);
}

// round 7
// speedup vs baseline: 3.3606x; 1.0371x over previous
#include <cuda_runtime.h>
#include <math.h>
#include <stdint.h>

// Problem constants
#define BB 4
#define TT 2048
#define BT (BB*TT)     // 8192
#define FF 512
#define HS 4
#define CS0 31
#define CS1 61
#define HALF0 15
#define HALF1 30
#define TCH 8          // tokens per window block (window_k)

#define W_SZ (FF*FF)
#define W2_0_SZ (HS*CS0*FF)
#define W2_1_SZ (HS*CS1*FF)
#define OFF_W1_0 0
#define OFF_W1_1 (W_SZ)
#define OFF_W3_0 (2*W_SZ)
#define OFF_W3_1 (3*W_SZ)
#define OFF_WOUT (4*W_SZ)
#define OFF_W2_0 (5*W_SZ)
#define OFF_W2_1 (5*W_SZ + W2_0_SZ)
#define WTF_TOTAL (5*W_SZ + W2_0_SZ + W2_1_SZ)

typedef unsigned long long ull;

// Scratch (device globals: alloc-free rule)
__device__ float g_qtf[BT*FF];
__device__ float g_vtf[BT*FF];
__device__ float g_wtf[WTF_TOTAL];
__device__ float g_rq0[BT*FF];
__device__ float g_rq1[BT*FF];
__device__ float g_v0 [BT*FF];
__device__ float g_v1 [BT*FF];
__device__ float g_mix[BT*FF];
__device__ float g_attn0[BT*HS*CS0];   // raw logits, softmaxed in window_k
__device__ float g_attn1[BT*HS*CS1];

__device__ __forceinline__ unsigned f2tf(float x) {
    unsigned r;
    asm("cvt.rna.tf32.f32 %0, %1;" : "=r"(r) : "f"(x));
    return r;
}
__device__ __forceinline__ float f2tf_f(float x) {
    return __uint_as_float(f2tf(x));
}

__device__ __forceinline__ ull pk2(float lo, float hi) {
    ull r;
    asm("mov.b64 %0, {%1, %2};" : "=l"(r) : "f"(lo), "f"(hi));
    return r;
}
__device__ __forceinline__ void upk2(float& lo, float& hi, ull v) {
    asm("mov.b64 {%0, %1}, %2;" : "=f"(lo), "=f"(hi) : "l"(v));
}
__device__ __forceinline__ ull ffma2(ull a, ull b, ull c) {
    ull d;
    asm("fma.rn.f32x2 %0, %1, %2, %3;" : "=l"(d) : "l"(a), "l"(b), "l"(c));
    return d;
}

__device__ __forceinline__ void mma_tf32(float c[4], unsigned a0, unsigned a1,
                                         unsigned a2, unsigned a3,
                                         unsigned b0, unsigned b1) {
    asm volatile(
        "mma.sync.aligned.m16n8k8.row.col.f32.tf32.tf32.f32 "
        "{%0,%1,%2,%3}, {%4,%5,%6,%7}, {%8,%9}, {%0,%1,%2,%3};"
        : "+f"(c[0]), "+f"(c[1]), "+f"(c[2]), "+f"(c[3])
        : "r"(a0), "r"(a1), "r"(a2), "r"(a3), "r"(b0), "r"(b1));
}

__device__ __forceinline__ void cp16(float* dst_smem, const float* src, bool pred) {
    unsigned d = (unsigned)__cvta_generic_to_shared(dst_smem);
    int sz = pred ? 16 : 0;
    asm volatile("cp.async.cg.shared.global [%0], [%1], 16, %2;"
                 :: "r"(d), "l"(src), "r"(sz));
}
__device__ __forceinline__ void cp_commit() {
    asm volatile("cp.async.commit_group;");
}

// ---------------------------------------------------------------------------
// tf32 rna-rounding prepass (inputs + weights only; cheap)
// ---------------------------------------------------------------------------
struct RDesc { const float* s; float* d; int n4; };
struct RArgs { RDesc r[9]; };

__global__ void round_k(RArgs a)
{
    RDesc t = a.r[blockIdx.z];
    int stride = gridDim.x * blockDim.x;
    for (int i = blockIdx.x * blockDim.x + threadIdx.x; i < t.n4; i += stride) {
        float4 v = ((const float4*)t.s)[i];
        ((uint4*)t.d)[i] = make_uint4(f2tf(v.x), f2tf(v.y), f2tf(v.z), f2tf(v.w));
    }
}

// ---------------------------------------------------------------------------
// Batched tf32 GEMM: C[M,N] = act( A[M,K] @ B[N,K]^T ).
// Inputs already tf32-rounded (raw bits). No cvt in mainloop.
// cp.async 3-stage. Block 128x128x32, 8 warps, warp tile 32x64.
// flags: bit0 = relu, bit1 = round output to tf32
// ---------------------------------------------------------------------------
struct GemmDesc { const float* A; const float* B; float* C; int N; int flags; };
struct GemmArgs { GemmDesc d[4]; };

#define BM 128
#define BN 128
#define BK 32
#define STR 36
#define A_STG (BM*STR)
#define B_STG (BN*STR)
#define GEMM_SMEM (3*(A_STG + B_STG)*4)   // 110592 bytes

__global__ __launch_bounds__(256, 2)
void gemm_mma(GemmArgs args, int K)
{
    GemmDesc g = args.d[blockIdx.z];
    const int bn = blockIdx.x * BN;
    if (bn >= g.N) return;
    const int bm = blockIdx.y * BM;

    extern __shared__ float sm[];
    float* As = sm;
    float* Bs = sm + 3 * A_STG;

    const int tid  = threadIdx.x;
    const int lane = tid & 31;
    const int warp = tid >> 5;
    const int wm   = warp >> 1;
    const int wn   = warp & 1;
    const int gid  = lane >> 2;
    const int quad = lane & 3;

    const int NT = K / BK;

    auto load_stage = [&](int s, int k0) {
        float* a = As + s * A_STG;
#pragma unroll
        for (int i = 0; i < 4; i++) {
            int id = tid + i * 256;
            int r  = id >> 3;
            int c  = (id & 7) * 4;
            cp16(a + r * STR + c, g.A + (size_t)(bm + r) * K + k0 + c, true);
        }
        float* b = Bs + s * B_STG;
#pragma unroll
        for (int i = 0; i < 4; i++) {
            int id = tid + i * 256;
            int r  = id >> 3;
            int c  = (id & 7) * 4;
            bool ok = (bn + r) < g.N;
            const float* src = ok ? (g.B + (size_t)(bn + r) * K + k0 + c) : g.B;
            cp16(b + r * STR + c, src, ok);
        }
        cp_commit();
    };

    float acc[2][8][4];
#pragma unroll
    for (int mt = 0; mt < 2; mt++)
#pragma unroll
        for (int nt = 0; nt < 8; nt++)
#pragma unroll
            for (int i = 0; i < 4; i++) acc[mt][nt][i] = 0.f;

    load_stage(0, 0);
    load_stage(1, BK);

    for (int kt = 0; kt < NT; kt++) {
        if (kt == NT - 1)
            asm volatile("cp.async.wait_group 0;");
        else
            asm volatile("cp.async.wait_group 1;");
        __syncthreads();

        if (kt + 2 < NT)
            load_stage((kt + 2) % 3, (kt + 2) * BK);

        const unsigned* Au = (const unsigned*)(As + (kt % 3) * A_STG);
        const unsigned* Bu = (const unsigned*)(Bs + (kt % 3) * B_STG);

#pragma unroll
        for (int kk = 0; kk < BK; kk += 8) {
            unsigned a[2][4], b[8][2];
#pragma unroll
            for (int mt = 0; mt < 2; mt++) {
                int r = wm * 32 + mt * 16 + gid;
                int c = kk + quad;
                a[mt][0] = Au[r * STR + c];
                a[mt][1] = Au[(r + 8) * STR + c];
                a[mt][2] = Au[r * STR + c + 4];
                a[mt][3] = Au[(r + 8) * STR + c + 4];
            }
#pragma unroll
            for (int nt = 0; nt < 8; nt++) {
                int n = wn * 64 + nt * 8 + gid;
                int c = kk + quad;
                b[nt][0] = Bu[n * STR + c];
                b[nt][1] = Bu[n * STR + c + 4];
            }
#pragma unroll
            for (int mt = 0; mt < 2; mt++)
#pragma unroll
                for (int nt = 0; nt < 8; nt++)
                    mma_tf32(acc[mt][nt], a[mt][0], a[mt][1], a[mt][2], a[mt][3],
                             b[nt][0], b[nt][1]);
        }
        __syncthreads();
    }

    const int relu = g.flags & 1;
    const int rnd  = g.flags & 2;
#pragma unroll
    for (int mt = 0; mt < 2; mt++) {
        int r0 = bm + wm * 32 + mt * 16 + gid;
#pragma unroll
        for (int nt = 0; nt < 8; nt++) {
            int c0 = bn + wn * 64 + nt * 8 + quad * 2;
            float v0 = acc[mt][nt][0], v1 = acc[mt][nt][1];
            float v2 = acc[mt][nt][2], v3 = acc[mt][nt][3];
            if (relu) {
                v0 = fmaxf(v0, 0.f); v1 = fmaxf(v1, 0.f);
                v2 = fmaxf(v2, 0.f); v3 = fmaxf(v3, 0.f);
            }
            if (rnd) {
                v0 = f2tf_f(v0); v1 = f2tf_f(v1);
                v2 = f2tf_f(v2); v3 = f2tf_f(v3);
            }
            if (c0 < g.N) {
                g.C[(size_t)r0 * g.N + c0]       = v0;
                g.C[(size_t)(r0 + 8) * g.N + c0] = v2;
            }
            if (c0 + 1 < g.N) {
                g.C[(size_t)r0 * g.N + c0 + 1]       = v1;
                g.C[(size_t)(r0 + 8) * g.N + c0 + 1] = v3;
            }
        }
    }
}

// ---------------------------------------------------------------------------
// Windowed attention apply + fused softmax + scale mix.
// 128 threads x 4 features/thread (float4 v loads, fma.rn.f32x2 math).
// Coefficients stored pre-duplicated in smem as {c,c} u64 -> 1 LDS.64 serves
// 2 FFMA2 = 4 outputs. Fully unrolled r-loops fold window predicates.
// Output mix rounded to tf32 (A of final GEMM).
// ---------------------------------------------------------------------------
__global__ __launch_bounds__(128)
void window_k(const float* __restrict__ sw_in)
{
    __shared__ float sp0[TCH * HS * CS0];     // plain logits scale 0
    __shared__ float sp1[TCH * HS * CS1];     // plain logits scale 1
    __shared__ ull   sd0[TCH * HS * CS0];     // duplicated softmax coeffs
    __shared__ ull   sd1[TCH * HS * CS1];
    __shared__ float ssw[2];

    int t0g = blockIdx.x * TCH;
    int b   = t0g / TT;
    int t0  = t0g - b * TT;
    int tid = threadIdx.x;

    for (int i = tid; i < TCH * HS * CS0; i += 128)
        sp0[i] = g_attn0[(size_t)t0g * (HS * CS0) + i];
    for (int i = tid; i < TCH * HS * CS1; i += 128)
        sp1[i] = g_attn1[(size_t)t0g * (HS * CS1) + i];
    if (tid == 0) {
        float a = sw_in[0], c = sw_in[1];
        float mx = fmaxf(a, c);
        float ea = __expf(a - mx), ec = __expf(c - mx);
        float inv = 1.f / (ea + ec);
        ssw[0] = ea * inv;
        ssw[1] = ec * inv;
    }
    __syncthreads();

    // fused softmax: warp-per-row; write duplicated {p,p} u64 coeffs
    {
        int warp = tid >> 5;
        int lane = tid & 31;
#pragma unroll
        for (int scale = 0; scale < 2; scale++) {
            int cs = scale ? CS1 : CS0;
            const float* pb = scale ? sp1 : sp0;
            ull* db = scale ? sd1 : sd0;
            for (int r = warp; r < TCH * HS; r += 4) {
                const float* p = pb + r * cs;
                ull* d = db + r * cs;
                float v0 = (lane      < cs) ? p[lane]      : -INFINITY;
                float v1 = (lane + 32 < cs) ? p[lane + 32] : -INFINITY;
                float m = fmaxf(v0, v1);
#pragma unroll
                for (int o = 16; o > 0; o >>= 1)
                    m = fmaxf(m, __shfl_xor_sync(0xFFFFFFFFu, m, o));
                float e0 = (lane      < cs) ? __expf(v0 - m) : 0.f;
                float e1 = (lane + 32 < cs) ? __expf(v1 - m) : 0.f;
                float s = e0 + e1;
#pragma unroll
                for (int o = 16; o > 0; o >>= 1)
                    s += __shfl_xor_sync(0xFFFFFFFFu, s, o);
                float inv = 1.f / s;
                if (lane < cs) {
                    float x = e0 * inv;
                    d[lane] = pk2(x, x);
                }
                if (lane + 32 < cs) {
                    float x = e1 * inv;
                    d[lane + 32] = pk2(x, x);
                }
            }
        }
    }
    __syncthreads();

    int f4 = tid * 4;            // first of 4 features owned by this thread
    int h  = f4 >> 7;            // head (uniform per warp)
    const float* v0b = g_v0 + ((size_t)b * TT) * FF + f4;
    const float* v1b = g_v1 + ((size_t)b * TT) * FF + f4;
    const ull* c0d = sd0 + h * CS0;
    const ull* c1d = sd1 + h * CS1;

    ull acc0[TCH][2], acc1[TCH][2];
#pragma unroll
    for (int j = 0; j < TCH; j++) {
        acc0[j][0] = 0ULL; acc0[j][1] = 0ULL;
        acc1[j][0] = 0ULL; acc1[j][1] = 0ULL;
    }

#pragma unroll
    for (int r = 0; r < TCH - 1 + CS0; r++) {
        int tp = t0 + r - HALF0;
        float4 vv = make_float4(0.f, 0.f, 0.f, 0.f);
        if ((unsigned)tp < (unsigned)TT)
            vv = *(const float4*)(v0b + (size_t)tp * FF);
        ull v01 = pk2(vv.x, vv.y);
        ull v23 = pk2(vv.z, vv.w);
#pragma unroll
        for (int j = 0; j < TCH; j++) {
            int c = r - j;
            if (c >= 0 && c < CS0) {     // compile-time after unroll
                ull cf = c0d[j * (HS * CS0) + c];
                acc0[j][0] = ffma2(cf, v01, acc0[j][0]);
                acc0[j][1] = ffma2(cf, v23, acc0[j][1]);
            }
        }
    }
#pragma unroll
    for (int r = 0; r < TCH - 1 + CS1; r++) {
        int tp = t0 + r - HALF1;
        float4 vv = make_float4(0.f, 0.f, 0.f, 0.f);
        if ((unsigned)tp < (unsigned)TT)
            vv = *(const float4*)(v1b + (size_t)tp * FF);
        ull v01 = pk2(vv.x, vv.y);
        ull v23 = pk2(vv.z, vv.w);
#pragma unroll
        for (int j = 0; j < TCH; j++) {
            int c = r - j;
            if (c >= 0 && c < CS1) {     // compile-time after unroll
                ull cf = c1d[j * (HS * CS1) + c];
                acc1[j][0] = ffma2(cf, v01, acc1[j][0]);
                acc1[j][1] = ffma2(cf, v23, acc1[j][1]);
            }
        }
    }

    float s0 = ssw[0], s1 = ssw[1];
#pragma unroll
    for (int j = 0; j < TCH; j++) {
        float a0x, a0y, a0z, a0w, a1x, a1y, a1z, a1w;
        upk2(a0x, a0y, acc0[j][0]);
        upk2(a0z, a0w, acc0[j][1]);
        upk2(a1x, a1y, acc1[j][0]);
        upk2(a1z, a1w, acc1[j][1]);
        uint4 o = make_uint4(f2tf(s0 * a0x + s1 * a1x),
                             f2tf(s0 * a0y + s1 * a1y),
                             f2tf(s0 * a0z + s1 * a1z),
                             f2tf(s0 * a0w + s1 * a1w));
        *(uint4*)&g_mix[(size_t)(t0g + j) * FF + f4] = o;
    }
}

// ---------------------------------------------------------------------------
extern "C" void kernel_launch(void* const* d_in, const int* in_sizes, int n_in,
                              void* d_out, int out_size)
{
    const float* query = (const float*)d_in[0];
    // d_in[1] = key (unused by reference)
    const float* value = (const float*)d_in[2];
    const float* w1_0  = (const float*)d_in[3];
    const float* w1_1  = (const float*)d_in[4];
    const float* w2_0  = (const float*)d_in[5];
    const float* w2_1  = (const float*)d_in[6];
    const float* w3_0  = (const float*)d_in[7];
    const float* w3_1  = (const float*)d_in[8];
    const float* sw    = (const float*)d_in[9];
    const float* w_out = (const float*)d_in[10];
    float* out = (float*)d_out;

    float *qtf, *vtf, *wtf, *rq0, *rq1, *v0, *v1, *mix, *a0, *a1;
    cudaGetSymbolAddress((void**)&qtf, g_qtf);
    cudaGetSymbolAddress((void**)&vtf, g_vtf);
    cudaGetSymbolAddress((void**)&wtf, g_wtf);
    cudaGetSymbolAddress((void**)&rq0, g_rq0);
    cudaGetSymbolAddress((void**)&rq1, g_rq1);
    cudaGetSymbolAddress((void**)&v0,  g_v0);
    cudaGetSymbolAddress((void**)&v1,  g_v1);
    cudaGetSymbolAddress((void**)&mix, g_mix);
    cudaGetSymbolAddress((void**)&a0,  g_attn0);
    cudaGetSymbolAddress((void**)&a1,  g_attn1);

    static bool attr_done = false;
    if (!attr_done) {
        cudaFuncSetAttribute(gemm_mma, cudaFuncAttributeMaxDynamicSharedMemorySize,
                             GEMM_SMEM);
        attr_done = true;
    }

    // 1) tf32 rounding prepass (inputs + weights)
    RArgs ra;
    ra.r[0] = {query, qtf, BT * FF / 4};
    ra.r[1] = {value, vtf, BT * FF / 4};
    ra.r[2] = {w1_0, wtf + OFF_W1_0, W_SZ / 4};
    ra.r[3] = {w1_1, wtf + OFF_W1_1, W_SZ / 4};
    ra.r[4] = {w3_0, wtf + OFF_W3_0, W_SZ / 4};
    ra.r[5] = {w3_1, wtf + OFF_W3_1, W_SZ / 4};
    ra.r[6] = {w_out, wtf + OFF_WOUT, W_SZ / 4};
    ra.r[7] = {w2_0, wtf + OFF_W2_0, W2_0_SZ / 4};
    ra.r[8] = {w2_1, wtf + OFF_W2_1, W2_1_SZ / 4};
    round_k<<<dim3(192, 1, 9), 256>>>(ra);

    // 2) 4 big GEMMs: q=relu(query@w1^T) [rounded], v=value@w3^T [raw fp32 out]
    GemmArgs gb;
    gb.d[0] = {qtf, wtf + OFF_W1_0, rq0, FF, 1 | 2};
    gb.d[1] = {qtf, wtf + OFF_W1_1, rq1, FF, 1 | 2};
    gb.d[2] = {vtf, wtf + OFF_W3_0, v0,  FF, 0};
    gb.d[3] = {vtf, wtf + OFF_W3_1, v1,  FF, 0};
    gemm_mma<<<dim3(FF / BN, BT / BM, 4), 256, GEMM_SMEM>>>(gb, FF);

    // 3) logits GEMMs (raw logits; softmax fused into window_k)
    GemmArgs gl;
    gl.d[0] = {rq0, wtf + OFF_W2_0, a0, HS * CS0, 0};
    gl.d[1] = {rq1, wtf + OFF_W2_1, a1, HS * CS1, 0};
    gl.d[2] = gl.d[0]; gl.d[3] = gl.d[0];
    gemm_mma<<<dim3((HS * CS1 + BN - 1) / BN, BT / BM, 2), 256, GEMM_SMEM>>>(gl, FF);

    // 4) fused softmax + window apply + scale mixing (mix rounded to tf32)
    window_k<<<BT / TCH, 128>>>(sw);

    // 5) final projection
    GemmArgs gf;
    gf.d[0] = {mix, wtf + OFF_WOUT, out, FF, 0};
    gf.d[1] = gf.d[0]; gf.d[2] = gf.d[0]; gf.d[3] = gf.d[0];
    gemm_mma<<<dim3(FF / BN, BT / BM, 1), 256, GEMM_SMEM>>>(gf, FF);
}

// round 8
// speedup vs baseline: 3.3925x; 1.0095x over previous
#include <cuda_runtime.h>
#include <math.h>
#include <stdint.h>

// Problem constants
#define BB 4
#define TT 2048
#define BT (BB*TT)     // 8192
#define FF 512
#define HS 4
#define CS0 31
#define CS1 61
#define HALF0 15
#define HALF1 30
#define TCH 8          // tokens per window block (window_k)

#define W_SZ (FF*FF)
#define W2_0_SZ (HS*CS0*FF)
#define W2_1_SZ (HS*CS1*FF)
#define OFF_W1_0 0
#define OFF_W1_1 (W_SZ)
#define OFF_W3_0 (2*W_SZ)
#define OFF_W3_1 (3*W_SZ)
#define OFF_WOUT (4*W_SZ)
#define OFF_W2_0 (5*W_SZ)
#define OFF_W2_1 (5*W_SZ + W2_0_SZ)
#define WTF_TOTAL (5*W_SZ + W2_0_SZ + W2_1_SZ)

typedef unsigned long long ull;

// Scratch (device globals: alloc-free rule)
__device__ float g_qtf[BT*FF];
__device__ float g_vtf[BT*FF];
__device__ float g_wtf[WTF_TOTAL];
__device__ float g_rq0[BT*FF];
__device__ float g_rq1[BT*FF];
__device__ float g_v0 [BT*FF];
__device__ float g_v1 [BT*FF];
__device__ float g_mix[BT*FF];
__device__ float g_attn0[BT*HS*CS0];   // raw logits, softmaxed in window_k
__device__ float g_attn1[BT*HS*CS1];

__device__ __forceinline__ unsigned f2tf(float x) {
    unsigned r;
    asm("cvt.rna.tf32.f32 %0, %1;" : "=r"(r) : "f"(x));
    return r;
}
__device__ __forceinline__ float f2tf_f(float x) {
    return __uint_as_float(f2tf(x));
}

__device__ __forceinline__ ull pk2(float lo, float hi) {
    ull r;
    asm("mov.b64 %0, {%1, %2};" : "=l"(r) : "f"(lo), "f"(hi));
    return r;
}
__device__ __forceinline__ void upk2(float& lo, float& hi, ull v) {
    asm("mov.b64 {%0, %1}, %2;" : "=f"(lo), "=f"(hi) : "l"(v));
}
__device__ __forceinline__ ull ffma2(ull a, ull b, ull c) {
    ull d;
    asm("fma.rn.f32x2 %0, %1, %2, %3;" : "=l"(d) : "l"(a), "l"(b), "l"(c));
    return d;
}

__device__ __forceinline__ void mma_tf32(float c[4], unsigned a0, unsigned a1,
                                         unsigned a2, unsigned a3,
                                         unsigned b0, unsigned b1) {
    asm volatile(
        "mma.sync.aligned.m16n8k8.row.col.f32.tf32.tf32.f32 "
        "{%0,%1,%2,%3}, {%4,%5,%6,%7}, {%8,%9}, {%0,%1,%2,%3};"
        : "+f"(c[0]), "+f"(c[1]), "+f"(c[2]), "+f"(c[3])
        : "r"(a0), "r"(a1), "r"(a2), "r"(a3), "r"(b0), "r"(b1));
}

__device__ __forceinline__ void cp16(float* dst_smem, const float* src, bool pred) {
    unsigned d = (unsigned)__cvta_generic_to_shared(dst_smem);
    int sz = pred ? 16 : 0;
    asm volatile("cp.async.cg.shared.global [%0], [%1], 16, %2;"
                 :: "r"(d), "l"(src), "r"(sz));
}
__device__ __forceinline__ void cp_commit() {
    asm volatile("cp.async.commit_group;");
}

// ---------------------------------------------------------------------------
// tf32 rna-rounding prepass (inputs + weights only; cheap)
// ---------------------------------------------------------------------------
struct RDesc { const float* s; float* d; int n4; };
struct RArgs { RDesc r[9]; };

__global__ void round_k(RArgs a)
{
    RDesc t = a.r[blockIdx.z];
    int stride = gridDim.x * blockDim.x;
    for (int i = blockIdx.x * blockDim.x + threadIdx.x; i < t.n4; i += stride) {
        float4 v = ((const float4*)t.s)[i];
        ((uint4*)t.d)[i] = make_uint4(f2tf(v.x), f2tf(v.y), f2tf(v.z), f2tf(v.w));
    }
}

// ---------------------------------------------------------------------------
// Batched tf32 GEMM: C[M,N] = act( A[M,K] @ B[N,K]^T ).
// Inputs already tf32-rounded (raw bits). No cvt in mainloop.
// cp.async 3-stage. Block 128x128x32, 8 warps, warp tile 32x64.
// flags: bit0 = relu, bit1 = round output to tf32
// ---------------------------------------------------------------------------
struct GemmDesc { const float* A; const float* B; float* C; int N; int flags; };
struct GemmArgs { GemmDesc d[4]; };

#define BM 128
#define BN 128
#define BK 32
#define STR 36
#define A_STG (BM*STR)
#define B_STG (BN*STR)
#define GEMM_SMEM (3*(A_STG + B_STG)*4)   // 110592 bytes

__global__ __launch_bounds__(256, 2)
void gemm_mma(GemmArgs args, int K)
{
    GemmDesc g = args.d[blockIdx.z];
    const int bn = blockIdx.x * BN;
    if (bn >= g.N) return;
    const int bm = blockIdx.y * BM;

    extern __shared__ float sm[];
    float* As = sm;
    float* Bs = sm + 3 * A_STG;

    const int tid  = threadIdx.x;
    const int lane = tid & 31;
    const int warp = tid >> 5;
    const int wm   = warp >> 1;
    const int wn   = warp & 1;
    const int gid  = lane >> 2;
    const int quad = lane & 3;

    const int NT = K / BK;

    auto load_stage = [&](int s, int k0) {
        float* a = As + s * A_STG;
#pragma unroll
        for (int i = 0; i < 4; i++) {
            int id = tid + i * 256;
            int r  = id >> 3;
            int c  = (id & 7) * 4;
            cp16(a + r * STR + c, g.A + (size_t)(bm + r) * K + k0 + c, true);
        }
        float* b = Bs + s * B_STG;
#pragma unroll
        for (int i = 0; i < 4; i++) {
            int id = tid + i * 256;
            int r  = id >> 3;
            int c  = (id & 7) * 4;
            bool ok = (bn + r) < g.N;
            const float* src = ok ? (g.B + (size_t)(bn + r) * K + k0 + c) : g.B;
            cp16(b + r * STR + c, src, ok);
        }
        cp_commit();
    };

    float acc[2][8][4];
#pragma unroll
    for (int mt = 0; mt < 2; mt++)
#pragma unroll
        for (int nt = 0; nt < 8; nt++)
#pragma unroll
            for (int i = 0; i < 4; i++) acc[mt][nt][i] = 0.f;

    load_stage(0, 0);
    load_stage(1, BK);

    for (int kt = 0; kt < NT; kt++) {
        if (kt == NT - 1)
            asm volatile("cp.async.wait_group 0;");
        else
            asm volatile("cp.async.wait_group 1;");
        __syncthreads();

        if (kt + 2 < NT)
            load_stage((kt + 2) % 3, (kt + 2) * BK);

        const unsigned* Au = (const unsigned*)(As + (kt % 3) * A_STG);
        const unsigned* Bu = (const unsigned*)(Bs + (kt % 3) * B_STG);

#pragma unroll
        for (int kk = 0; kk < BK; kk += 8) {
            unsigned a[2][4], b[8][2];
#pragma unroll
            for (int mt = 0; mt < 2; mt++) {
                int r = wm * 32 + mt * 16 + gid;
                int c = kk + quad;
                a[mt][0] = Au[r * STR + c];
                a[mt][1] = Au[(r + 8) * STR + c];
                a[mt][2] = Au[r * STR + c + 4];
                a[mt][3] = Au[(r + 8) * STR + c + 4];
            }
#pragma unroll
            for (int nt = 0; nt < 8; nt++) {
                int n = wn * 64 + nt * 8 + gid;
                int c = kk + quad;
                b[nt][0] = Bu[n * STR + c];
                b[nt][1] = Bu[n * STR + c + 4];
            }
#pragma unroll
            for (int mt = 0; mt < 2; mt++)
#pragma unroll
                for (int nt = 0; nt < 8; nt++)
                    mma_tf32(acc[mt][nt], a[mt][0], a[mt][1], a[mt][2], a[mt][3],
                             b[nt][0], b[nt][1]);
        }
        __syncthreads();
    }

    const int relu = g.flags & 1;
    const int rnd  = g.flags & 2;
#pragma unroll
    for (int mt = 0; mt < 2; mt++) {
        int r0 = bm + wm * 32 + mt * 16 + gid;
#pragma unroll
        for (int nt = 0; nt < 8; nt++) {
            int c0 = bn + wn * 64 + nt * 8 + quad * 2;
            float v0 = acc[mt][nt][0], v1 = acc[mt][nt][1];
            float v2 = acc[mt][nt][2], v3 = acc[mt][nt][3];
            if (relu) {
                v0 = fmaxf(v0, 0.f); v1 = fmaxf(v1, 0.f);
                v2 = fmaxf(v2, 0.f); v3 = fmaxf(v3, 0.f);
            }
            if (rnd) {
                v0 = f2tf_f(v0); v1 = f2tf_f(v1);
                v2 = f2tf_f(v2); v3 = f2tf_f(v3);
            }
            if (c0 < g.N) {
                g.C[(size_t)r0 * g.N + c0]       = v0;
                g.C[(size_t)(r0 + 8) * g.N + c0] = v2;
            }
            if (c0 + 1 < g.N) {
                g.C[(size_t)r0 * g.N + c0 + 1]       = v1;
                g.C[(size_t)(r0 + 8) * g.N + c0 + 1] = v3;
            }
        }
    }
}

// ---------------------------------------------------------------------------
// Windowed attention apply + fused softmax + scale mix.
// 256 threads x 2 features/thread (float2 v loads, fma.rn.f32x2 math).
// Softmax reads logits directly from global; duplicated {c,c} u64 coeffs in
// smem -> 1 LDS.64 broadcast serves 1 FFMA2 = 2 outputs.
// Fully unrolled r-loops fold window predicates at compile time.
// Output mix rounded to tf32 (A of final GEMM).
// ---------------------------------------------------------------------------
__global__ __launch_bounds__(256)
void window_k(const float* __restrict__ sw_in)
{
    __shared__ ull   sd0[TCH * HS * CS0];     // duplicated softmax coeffs
    __shared__ ull   sd1[TCH * HS * CS1];
    __shared__ float ssw[2];

    int t0g = blockIdx.x * TCH;
    int b   = t0g / TT;
    int t0  = t0g - b * TT;
    int tid = threadIdx.x;

    if (tid == 0) {
        float a = sw_in[0], c = sw_in[1];
        float mx = fmaxf(a, c);
        float ea = __expf(a - mx), ec = __expf(c - mx);
        float inv = 1.f / (ea + ec);
        ssw[0] = ea * inv;
        ssw[1] = ec * inv;
    }

    // fused softmax: warp-per-row, logits straight from global
    {
        int warp = tid >> 5;
        int lane = tid & 31;
#pragma unroll
        for (int scale = 0; scale < 2; scale++) {
            int cs = scale ? CS1 : CS0;
            const float* gb = scale ? (g_attn1 + (size_t)t0g * (HS * CS1))
                                    : (g_attn0 + (size_t)t0g * (HS * CS0));
            ull* db = scale ? sd1 : sd0;
            for (int r = warp; r < TCH * HS; r += 8) {
                const float* p = gb + r * cs;
                ull* d = db + r * cs;
                float v0 = (lane      < cs) ? p[lane]      : -INFINITY;
                float v1 = (lane + 32 < cs) ? p[lane + 32] : -INFINITY;
                float m = fmaxf(v0, v1);
#pragma unroll
                for (int o = 16; o > 0; o >>= 1)
                    m = fmaxf(m, __shfl_xor_sync(0xFFFFFFFFu, m, o));
                float e0 = (lane      < cs) ? __expf(v0 - m) : 0.f;
                float e1 = (lane + 32 < cs) ? __expf(v1 - m) : 0.f;
                float s = e0 + e1;
#pragma unroll
                for (int o = 16; o > 0; o >>= 1)
                    s += __shfl_xor_sync(0xFFFFFFFFu, s, o);
                float inv = 1.f / s;
                if (lane < cs) {
                    float x = e0 * inv;
                    d[lane] = pk2(x, x);
                }
                if (lane + 32 < cs) {
                    float x = e1 * inv;
                    d[lane + 32] = pk2(x, x);
                }
            }
        }
    }
    __syncthreads();

    int f2 = tid * 2;            // first of 2 features owned by this thread
    int h  = f2 >> 7;            // head (uniform per warp)
    const float* v0b = g_v0 + ((size_t)b * TT) * FF + f2;
    const float* v1b = g_v1 + ((size_t)b * TT) * FF + f2;
    const ull* c0d = sd0 + h * CS0;
    const ull* c1d = sd1 + h * CS1;

    ull acc0[TCH], acc1[TCH];
#pragma unroll
    for (int j = 0; j < TCH; j++) { acc0[j] = 0ULL; acc1[j] = 0ULL; }

#pragma unroll
    for (int r = 0; r < TCH - 1 + CS0; r++) {
        int tp = t0 + r - HALF0;
        float2 vv = make_float2(0.f, 0.f);
        if ((unsigned)tp < (unsigned)TT)
            vv = *(const float2*)(v0b + (size_t)tp * FF);
        ull v01 = pk2(vv.x, vv.y);
#pragma unroll
        for (int j = 0; j < TCH; j++) {
            int c = r - j;
            if (c >= 0 && c < CS0)       // compile-time after unroll
                acc0[j] = ffma2(c0d[j * (HS * CS0) + c], v01, acc0[j]);
        }
    }
#pragma unroll
    for (int r = 0; r < TCH - 1 + CS1; r++) {
        int tp = t0 + r - HALF1;
        float2 vv = make_float2(0.f, 0.f);
        if ((unsigned)tp < (unsigned)TT)
            vv = *(const float2*)(v1b + (size_t)tp * FF);
        ull v01 = pk2(vv.x, vv.y);
#pragma unroll
        for (int j = 0; j < TCH; j++) {
            int c = r - j;
            if (c >= 0 && c < CS1)       // compile-time after unroll
                acc1[j] = ffma2(c1d[j * (HS * CS1) + c], v01, acc1[j]);
        }
    }

    float s0 = ssw[0], s1 = ssw[1];
#pragma unroll
    for (int j = 0; j < TCH; j++) {
        float a0x, a0y, a1x, a1y;
        upk2(a0x, a0y, acc0[j]);
        upk2(a1x, a1y, acc1[j]);
        uint2 o = make_uint2(f2tf(s0 * a0x + s1 * a1x),
                             f2tf(s0 * a0y + s1 * a1y));
        *(uint2*)&g_mix[(size_t)(t0g + j) * FF + f2] = o;
    }
}

// ---------------------------------------------------------------------------
extern "C" void kernel_launch(void* const* d_in, const int* in_sizes, int n_in,
                              void* d_out, int out_size)
{
    const float* query = (const float*)d_in[0];
    // d_in[1] = key (unused by reference)
    const float* value = (const float*)d_in[2];
    const float* w1_0  = (const float*)d_in[3];
    const float* w1_1  = (const float*)d_in[4];
    const float* w2_0  = (const float*)d_in[5];
    const float* w2_1  = (const float*)d_in[6];
    const float* w3_0  = (const float*)d_in[7];
    const float* w3_1  = (const float*)d_in[8];
    const float* sw    = (const float*)d_in[9];
    const float* w_out = (const float*)d_in[10];
    float* out = (float*)d_out;

    float *qtf, *vtf, *wtf, *rq0, *rq1, *v0, *v1, *mix, *a0, *a1;
    cudaGetSymbolAddress((void**)&qtf, g_qtf);
    cudaGetSymbolAddress((void**)&vtf, g_vtf);
    cudaGetSymbolAddress((void**)&wtf, g_wtf);
    cudaGetSymbolAddress((void**)&rq0, g_rq0);
    cudaGetSymbolAddress((void**)&rq1, g_rq1);
    cudaGetSymbolAddress((void**)&v0,  g_v0);
    cudaGetSymbolAddress((void**)&v1,  g_v1);
    cudaGetSymbolAddress((void**)&mix, g_mix);
    cudaGetSymbolAddress((void**)&a0,  g_attn0);
    cudaGetSymbolAddress((void**)&a1,  g_attn1);

    static bool attr_done = false;
    if (!attr_done) {
        cudaFuncSetAttribute(gemm_mma, cudaFuncAttributeMaxDynamicSharedMemorySize,
                             GEMM_SMEM);
        attr_done = true;
    }

    // 1) tf32 rounding prepass (inputs + weights)
    RArgs ra;
    ra.r[0] = {query, qtf, BT * FF / 4};
    ra.r[1] = {value, vtf, BT * FF / 4};
    ra.r[2] = {w1_0, wtf + OFF_W1_0, W_SZ / 4};
    ra.r[3] = {w1_1, wtf + OFF_W1_1, W_SZ / 4};
    ra.r[4] = {w3_0, wtf + OFF_W3_0, W_SZ / 4};
    ra.r[5] = {w3_1, wtf + OFF_W3_1, W_SZ / 4};
    ra.r[6] = {w_out, wtf + OFF_WOUT, W_SZ / 4};
    ra.r[7] = {w2_0, wtf + OFF_W2_0, W2_0_SZ / 4};
    ra.r[8] = {w2_1, wtf + OFF_W2_1, W2_1_SZ / 4};
    round_k<<<dim3(192, 1, 9), 256>>>(ra);

    // 2) 4 big GEMMs: q=relu(query@w1^T) [rounded], v=value@w3^T [raw fp32 out]
    GemmArgs gb;
    gb.d[0] = {qtf, wtf + OFF_W1_0, rq0, FF, 1 | 2};
    gb.d[1] = {qtf, wtf + OFF_W1_1, rq1, FF, 1 | 2};
    gb.d[2] = {vtf, wtf + OFF_W3_0, v0,  FF, 0};
    gb.d[3] = {vtf, wtf + OFF_W3_1, v1,  FF, 0};
    gemm_mma<<<dim3(FF / BN, BT / BM, 4), 256, GEMM_SMEM>>>(gb, FF);

    // 3) logits GEMMs (raw logits; softmax fused into window_k)
    GemmArgs gl;
    gl.d[0] = {rq0, wtf + OFF_W2_0, a0, HS * CS0, 0};
    gl.d[1] = {rq1, wtf + OFF_W2_1, a1, HS * CS1, 0};
    gl.d[2] = gl.d[0]; gl.d[3] = gl.d[0];
    gemm_mma<<<dim3((HS * CS1 + BN - 1) / BN, BT / BM, 2), 256, GEMM_SMEM>>>(gl, FF);

    // 4) fused softmax + window apply + scale mixing (mix rounded to tf32)
    window_k<<<BT / TCH, 256>>>(sw);

    // 5) final projection
    GemmArgs gf;
    gf.d[0] = {mix, wtf + OFF_WOUT, out, FF, 0};
    gf.d[1] = gf.d[0]; gf.d[2] = gf.d[0]; gf.d[3] = gf.d[0];
    gemm_mma<<<dim3(FF / BN, BT / BM, 1), 256, GEMM_SMEM>>>(gf, FF);
}